// round 2
// baseline (speedup 1.0000x reference)
#include <cuda_runtime.h>
#include <math.h>

#define BB   1024
#define TT   256
#define DH   128
#define G3   384
#define DIN  129
#define DX   64
#define DEPS 16

// ---- scratch (device globals: no runtime allocation allowed) ----
__device__ float g_xenc[BB * DX];                       // 256 KB
__device__ float g_h0[BB * DH];                         // 512 KB
__device__ float g_gates[(size_t)BB * TT * G3];         // 402 MB

// ============================================================================
// K1: x_enc = x @ Wx^T + bx ; h0 = tanh([x_enc, eps[:,0,:]] @ W0^T + b0)
// one block per batch row, 128 threads
// ============================================================================
__global__ void k_enc(const float* __restrict__ x,  const float* __restrict__ Wx,
                      const float* __restrict__ bx, const float* __restrict__ eps,
                      const float* __restrict__ W0, const float* __restrict__ b0) {
    __shared__ float xs[64], xe[64], e0[16];
    int b = blockIdx.x, tid = threadIdx.x;
    if (tid < 64)                 xs[tid]      = x[b * 64 + tid];
    if (tid >= 64 && tid < 80)    e0[tid - 64] = eps[(size_t)b * TT * DEPS + (tid - 64)];
    __syncthreads();
    if (tid < 64) {
        float acc = bx[tid];
        #pragma unroll
        for (int k = 0; k < 64; k++) acc = fmaf(Wx[tid * 64 + k], xs[k], acc);
        xe[tid] = acc;
        g_xenc[b * 64 + tid] = acc;
    }
    __syncthreads();
    float acc = b0[tid];
    #pragma unroll
    for (int k = 0; k < 64; k++) acc = fmaf(W0[tid * 80 + k], xe[k], acc);
    #pragma unroll
    for (int k = 0; k < 16; k++) acc = fmaf(W0[tid * 80 + 64 + k], e0[k], acc);
    g_h0[b * DH + tid] = tanhf(acc);
}

// ============================================================================
// K2: gates_x[row][g] = bih[g] + sum_k Wih[g][k] * inp[row][k]
// inp[row] = [Ea[a] | Et[t] | x_enc | eps | prev_y], row = b*T + t
// block tile: 128 rows x 128 gates, 256 threads, 8x8 register micro-tile
// grid = (BT/128, 3)
// ============================================================================
#define K2_SMEM ((129 * 132 + 128 * 132) * 4)

__global__ void k_gates(const int* __restrict__ a, const int* __restrict__ tt,
                        const float* __restrict__ y, const float* __restrict__ eps,
                        const float* __restrict__ Ea, const float* __restrict__ Et,
                        const float* __restrict__ Wih, const float* __restrict__ bih) {
    extern __shared__ float sm[];
    float* Wt  = sm;               // [129][132]  Wt[k][g] = Wih[g0+g][k]
    float* inp = sm + 129 * 132;   // [128][132]

    int tid  = threadIdx.x;
    int g0   = blockIdx.y * 128;
    int row0 = blockIdx.x * 128;

    // load Wih tile transposed (global reads coalesced along k)
    for (int idx = tid; idx < 128 * 129; idx += 256) {
        int g = idx / 129, k = idx - g * 129;
        Wt[k * 132 + g] = Wih[(g0 + g) * 129 + k];
    }
    // build input rows in smem
    for (int idx = tid; idx < 128 * 129; idx += 256) {
        int r = idx / 129, k = idx - r * 129;
        int rowg = row0 + r;
        int b = rowg >> 8, s = rowg & 255;
        float v;
        if      (k < 32)  v = Ea[a[b * TT + s] * 32 + k];
        else if (k < 48)  v = Et[tt[b * TT + s] * 16 + (k - 32)];
        else if (k < 112) v = g_xenc[b * 64 + (k - 48)];
        else if (k < 128) v = eps[((size_t)(b * TT + s)) * DEPS + (k - 112)];
        else              v = (s == 0) ? 0.f : y[b * TT + s - 1];
        inp[r * 132 + k] = v;
    }
    __syncthreads();

    int tx = tid & 15, ty = tid >> 4;   // tx: gate group (8 gates), ty: row group (8 rows)
    float acc[8][8];
    #pragma unroll
    for (int i = 0; i < 8; i++)
        #pragma unroll
        for (int j = 0; j < 8; j++) acc[i][j] = 0.f;

    const float* wcol = &Wt[tx * 8];
    for (int k = 0; k < 129; k++) {
        float4 w0 = *(const float4*)&wcol[k * 132];
        float4 w1 = *(const float4*)&wcol[k * 132 + 4];
        #pragma unroll
        for (int i = 0; i < 8; i++) {
            float av = inp[(ty * 8 + i) * 132 + k];
            acc[i][0] = fmaf(av, w0.x, acc[i][0]);
            acc[i][1] = fmaf(av, w0.y, acc[i][1]);
            acc[i][2] = fmaf(av, w0.z, acc[i][2]);
            acc[i][3] = fmaf(av, w0.w, acc[i][3]);
            acc[i][4] = fmaf(av, w1.x, acc[i][4]);
            acc[i][5] = fmaf(av, w1.y, acc[i][5]);
            acc[i][6] = fmaf(av, w1.z, acc[i][6]);
            acc[i][7] = fmaf(av, w1.w, acc[i][7]);
        }
    }

    int gbase = g0 + tx * 8;
    float4 bi0 = *(const float4*)&bih[gbase];
    float4 bi1 = *(const float4*)&bih[gbase + 4];
    #pragma unroll
    for (int i = 0; i < 8; i++) {
        size_t off = (size_t)(row0 + ty * 8 + i) * G3 + gbase;
        float4 o0 = make_float4(acc[i][0] + bi0.x, acc[i][1] + bi0.y,
                                acc[i][2] + bi0.z, acc[i][3] + bi0.w);
        float4 o1 = make_float4(acc[i][4] + bi1.x, acc[i][5] + bi1.y,
                                acc[i][6] + bi1.z, acc[i][7] + bi1.w);
        *(float4*)&g_gates[off]     = o0;
        *(float4*)&g_gates[off + 4] = o1;
    }
}

// ============================================================================
// K3: GRU scan, persistent per-batch-slice blocks (no inter-block deps).
// 128 blocks x 384 threads; each block owns 8 batch rows for all 256 steps.
// Whh cached in SMEM in float4-chunk layout: W4[kc*384 + j] = Whh[j][4kc..4kc+3]
// Fused epilogue: logits = h @ Wy^T + by, prob = sigmoid (mask==identity fwd).
// ============================================================================
#define K3_SMEM ((384 * 128 + 1024 + 4 * 1024 + 128) * 4)

__global__ void __launch_bounds__(384, 1)
k_rnn(const float* __restrict__ Whh, const float* __restrict__ bhh,
      const float* __restrict__ Wy,  const float* __restrict__ by,
      float* __restrict__ out) {
    extern __shared__ float sm[];
    float4* W4  = (float4*)sm;            // 384*128 floats (as 384*32 float4)
    float*  hs  = sm + 384 * 128;         // [8][128] current hidden
    float*  As  = hs + 1024;              // r gate
    float*  Bs  = As + 1024;              // z gate
    float*  Cs  = Bs + 1024;              // gh_n (+bhh_n)
    float*  Ds  = Cs + 1024;              // gx_n
    float*  Wys = Ds + 1024;              // Wy [128]
    float4* h4  = (float4*)hs;

    int tid = threadIdx.x;
    int b0r = blockIdx.x * 8;

    // stage Whh into chunked-float4 layout (coalesced global reads)
    for (int idx = tid; idx < 384 * 128; idx += 384) {
        int j = idx >> 7, k = idx & 127;
        sm[(k >> 2) * 1536 + j * 4 + (k & 3)] = Whh[idx];
    }
    for (int i = tid; i < 1024; i += 384) hs[i] = g_h0[b0r * DH + i];
    if (tid < 128) Wys[tid] = Wy[tid];
    float bhh_j = bhh[tid];
    float by0   = by[0];
    __syncthreads();

    int sec = tid >> 7, jj = tid & 127;
    int warp = tid >> 5, lane = tid & 31;

    for (int t = 0; t < TT; t++) {
        // prefetch this step's input gates (coalesced, hidden under dot loop)
        float gx[8];
        #pragma unroll
        for (int r = 0; r < 8; r++)
            gx[r] = g_gates[((size_t)(b0r + r) * TT + t) * G3 + tid];

        // gh[r][tid] = Whh[tid] . h[r]
        float acc[8];
        #pragma unroll
        for (int r = 0; r < 8; r++) acc[r] = 0.f;
        #pragma unroll 8
        for (int kc = 0; kc < 32; kc++) {
            float4 w = W4[kc * 384 + tid];
            #pragma unroll
            for (int r = 0; r < 8; r++) {
                float4 h = h4[r * 32 + kc];
                acc[r] = fmaf(w.x, h.x, acc[r]);
                acc[r] = fmaf(w.y, h.y, acc[r]);
                acc[r] = fmaf(w.z, h.z, acc[r]);
                acc[r] = fmaf(w.w, h.w, acc[r]);
            }
        }

        #pragma unroll
        for (int r = 0; r < 8; r++) {
            float gh = acc[r] + bhh_j;
            if (sec == 0) {
                float pre = gx[r] + gh;
                As[r * 128 + jj] = 1.f / (1.f + expf(-pre));
            } else if (sec == 1) {
                float pre = gx[r] + gh;
                Bs[r * 128 + jj] = 1.f / (1.f + expf(-pre));
            } else {
                Cs[r * 128 + jj] = gh;
                Ds[r * 128 + jj] = gx[r];
            }
        }
        __syncthreads();

        // h_new = (1-z)*tanh(gxn + r*ghn) + z*h
        for (int i = tid; i < 1024; i += 384) {
            float rv = As[i], zv = Bs[i];
            float n  = tanhf(Ds[i] + rv * Cs[i]);
            hs[i] = (1.f - zv) * n + zv * hs[i];
        }
        __syncthreads();

        // logits + sigmoid, one warp per row
        if (warp < 8) {
            float s = 0.f;
            #pragma unroll
            for (int m = 0; m < 4; m++)
                s = fmaf(hs[warp * 128 + lane + m * 32], Wys[lane + m * 32], s);
            s += __shfl_down_sync(0xffffffffu, s, 16);
            s += __shfl_down_sync(0xffffffffu, s, 8);
            s += __shfl_down_sync(0xffffffffu, s, 4);
            s += __shfl_down_sync(0xffffffffu, s, 2);
            s += __shfl_down_sync(0xffffffffu, s, 1);
            if (lane == 0) {
                float logit = s + by0;
                size_t o = ((size_t)(b0r + warp) * TT + t) * 2;
                out[o]     = logit;
                out[o + 1] = 1.f / (1.f + expf(-logit));
            }
        }
        // no extra sync needed: next-step writes (As..Ds) are race-free with
        // this step's reads, and hs writes are gated behind next sync #1.
    }
}

// ============================================================================
extern "C" void kernel_launch(void* const* d_in, const int* in_sizes, int n_in,
                              void* d_out, int out_size) {
    const float* x   = (const float*)d_in[0];
    const int*   a   = (const int*)  d_in[1];
    const int*   t   = (const int*)  d_in[2];
    const float* y   = (const float*)d_in[3];
    // d_in[4] = mask: identity in forward pass
    const float* eps = (const float*)d_in[5];
    const float* Wx  = (const float*)d_in[6];
    const float* bx  = (const float*)d_in[7];
    const float* Ea  = (const float*)d_in[8];
    const float* Et  = (const float*)d_in[9];
    const float* Wih = (const float*)d_in[10];
    const float* Whh = (const float*)d_in[11];
    const float* bih = (const float*)d_in[12];
    const float* bhh = (const float*)d_in[13];
    const float* W0  = (const float*)d_in[14];
    const float* b0  = (const float*)d_in[15];
    const float* Wy  = (const float*)d_in[16];
    const float* by  = (const float*)d_in[17];
    float* out = (float*)d_out;

    cudaFuncSetAttribute(k_gates, cudaFuncAttributeMaxDynamicSharedMemorySize, K2_SMEM);
    cudaFuncSetAttribute(k_rnn,   cudaFuncAttributeMaxDynamicSharedMemorySize, K3_SMEM);

    k_enc<<<BB, 128>>>(x, Wx, bx, eps, W0, b0);

    dim3 g2(BB * TT / 128, 3);
    k_gates<<<g2, 256, K2_SMEM>>>(a, t, y, eps, Ea, Et, Wih, bih);

    k_rnn<<<BB / 8, 384, K3_SMEM>>>(Whh, bhh, Wy, by, out);
}

// round 3
// speedup vs baseline: 1.1161x; 1.1161x over previous
#include <cuda_runtime.h>
#include <math.h>

#define BB   1024
#define TT   256
#define DH   128
#define G3   384
#define DIN  129
#define DX   64
#define DEPS 16

typedef unsigned long long ull;

// packed fp32x2 FMA: d = a*b + d (elementwise on two packed floats)
__device__ __forceinline__ void fma2(ull& d, ull a, ull b) {
    asm("fma.rn.f32x2 %0, %1, %2, %0;" : "+l"(d) : "l"(a), "l"(b));
}
__device__ __forceinline__ float pairsum(ull v) {
    float lo, hi;
    asm("mov.b64 {%0, %1}, %2;" : "=f"(lo), "=f"(hi) : "l"(v));
    return lo + hi;
}

// ---- scratch (device globals: no runtime allocation allowed) ----
__device__ float g_xenc[BB * DX];
__device__ float g_h0[BB * DH];
__device__ float g_gates[(size_t)BB * TT * G3];   // 402 MB

// ============================================================================
// K1: x_enc = x @ Wx^T + bx ; h0 = tanh([x_enc, eps[:,0,:]] @ W0^T + b0)
// ============================================================================
__global__ void k_enc(const float* __restrict__ x,  const float* __restrict__ Wx,
                      const float* __restrict__ bx, const float* __restrict__ eps,
                      const float* __restrict__ W0, const float* __restrict__ b0) {
    __shared__ float xs[64], xe[64], e0[16];
    int b = blockIdx.x, tid = threadIdx.x;
    if (tid < 64)                 xs[tid]      = x[b * 64 + tid];
    if (tid >= 64 && tid < 80)    e0[tid - 64] = eps[(size_t)b * TT * DEPS + (tid - 64)];
    __syncthreads();
    if (tid < 64) {
        float acc = bx[tid];
        #pragma unroll
        for (int k = 0; k < 64; k++) acc = fmaf(Wx[tid * 64 + k], xs[k], acc);
        xe[tid] = acc;
        g_xenc[b * 64 + tid] = acc;
    }
    __syncthreads();
    float acc = b0[tid];
    #pragma unroll
    for (int k = 0; k < 64; k++) acc = fmaf(W0[tid * 80 + k], xe[k], acc);
    #pragma unroll
    for (int k = 0; k < 16; k++) acc = fmaf(W0[tid * 80 + 64 + k], e0[k], acc);
    g_h0[b * DH + tid] = tanhf(acc);
}

// ============================================================================
// K2: gates_x = inp @ Wih^T + bih   (f32x2 packed along K)
// block tile: 128 rows x 64 gates, 256 threads, 8x4 packed micro-tile
// grid = (3*DH/64 = 6 gate tiles, BT/128 = 2048 row tiles)
// ============================================================================
#define K2_SMEM ((128 * 132 + 65 * 64 * 2) * 4)

__global__ void k_gates(const int* __restrict__ a, const int* __restrict__ tt,
                        const float* __restrict__ y, const float* __restrict__ eps,
                        const float* __restrict__ Ea, const float* __restrict__ Et,
                        const float* __restrict__ Wih, const float* __restrict__ bih) {
    extern __shared__ float sm[];
    float* inp = sm;                 // [128][132] (k 129..131 zero-padded)
    float* Wt  = sm + 128 * 132;     // k-pairs: Wt[(kp*64+g)*2 + {0,1}]

    int tid  = threadIdx.x;
    int g0   = blockIdx.x * 64;
    int row0 = blockIdx.y * 128;

    // stage Wih tile as k-pairs (zero pad k=129)
    for (int idx = tid; idx < 64 * 65; idx += 256) {
        int g = idx / 65, kp = idx - g * 65;
        const float* wrow = &Wih[(g0 + g) * 129];
        float w0 = wrow[2 * kp];
        float w1 = (2 * kp + 1 < 129) ? wrow[2 * kp + 1] : 0.f;
        Wt[(kp * 64 + g) * 2]     = w0;
        Wt[(kp * 64 + g) * 2 + 1] = w1;
    }
    // build input rows in smem
    for (int idx = tid; idx < 128 * 132; idx += 256) {
        int r = idx / 132, k = idx - r * 132;
        int rowg = row0 + r;
        int b = rowg >> 8, s = rowg & 255;
        float v;
        if      (k < 32)  v = Ea[a[b * TT + s] * 32 + k];
        else if (k < 48)  v = Et[tt[b * TT + s] * 16 + (k - 32)];
        else if (k < 112) v = g_xenc[b * 64 + (k - 48)];
        else if (k < 128) v = eps[((size_t)(b * TT + s)) * DEPS + (k - 112)];
        else if (k == 128) v = (s == 0) ? 0.f : y[b * TT + s - 1];
        else              v = 0.f;
        inp[r * 132 + k] = v;
    }
    __syncthreads();

    int tx = tid & 15, ty = tid >> 4;   // tx: 4 gates, ty: 8 rows
    ull acc[8][4];
    #pragma unroll
    for (int i = 0; i < 8; i++)
        #pragma unroll
        for (int j = 0; j < 4; j++) acc[i][j] = 0ull;

    const float* wbase = &Wt[tx * 4 * 2];
    #pragma unroll 5
    for (int kp = 0; kp < 65; kp++) {
        ulonglong2 w01 = *(const ulonglong2*)&wbase[kp * 128 * 1];      // gates tx*4, tx*4+1
        ulonglong2 w23 = *(const ulonglong2*)&wbase[kp * 128 + 4];      // gates tx*4+2, tx*4+3
        #pragma unroll
        for (int i = 0; i < 8; i++) {
            ull av = *(const ull*)&inp[(ty * 8 + i) * 132 + 2 * kp];
            fma2(acc[i][0], av, w01.x);
            fma2(acc[i][1], av, w01.y);
            fma2(acc[i][2], av, w23.x);
            fma2(acc[i][3], av, w23.y);
        }
    }

    int gbase = g0 + tx * 4;
    float4 bi = *(const float4*)&bih[gbase];
    #pragma unroll
    for (int i = 0; i < 8; i++) {
        size_t off = (size_t)(row0 + ty * 8 + i) * G3 + gbase;
        float4 o = make_float4(pairsum(acc[i][0]) + bi.x,
                               pairsum(acc[i][1]) + bi.y,
                               pairsum(acc[i][2]) + bi.z,
                               pairsum(acc[i][3]) + bi.w);
        *(float4*)&g_gates[off] = o;
    }
}

// ============================================================================
// K3: GRU scan, persistent blocks; dot products in packed f32x2.
// 128 blocks x 384 threads, 8 batch rows/block, Whh resident in SMEM.
// ============================================================================
#define K3_SMEM ((384 * 128 + 1024 + 4 * 1024 + 128) * 4)

__global__ void __launch_bounds__(384, 1)
k_rnn(const float* __restrict__ Whh, const float* __restrict__ bhh,
      const float* __restrict__ Wy,  const float* __restrict__ by,
      float* __restrict__ out) {
    extern __shared__ float sm[];
    float*  hs  = sm + 384 * 128;         // [8][128] current hidden
    float*  As  = hs + 1024;              // r gate
    float*  Bs  = As + 1024;              // z gate
    float*  Cs  = Bs + 1024;              // gh_n
    float*  Ds  = Cs + 1024;              // gx_n
    float*  Wys = Ds + 1024;              // Wy [128]
    const ulonglong2* W2 = (const ulonglong2*)sm;   // Whh chunked: [32][384] float4
    const ulonglong2* h2 = (const ulonglong2*)hs;   // [8][32] float4

    int tid = threadIdx.x;
    int b0r = blockIdx.x * 8;

    // stage Whh into chunked-float4 layout: chunk kc holds Whh[j][4kc..4kc+3]
    for (int idx = tid; idx < 384 * 128; idx += 384) {
        int j = idx >> 7, k = idx & 127;
        sm[(k >> 2) * 1536 + j * 4 + (k & 3)] = Whh[idx];
    }
    for (int i = tid; i < 1024; i += 384) hs[i] = g_h0[b0r * DH + i];
    if (tid < 128) Wys[tid] = Wy[tid];
    float bhh_j = bhh[tid];
    float by0   = by[0];
    __syncthreads();

    int sec = tid >> 7, jj = tid & 127;
    int warp = tid >> 5, lane = tid & 31;

    for (int t = 0; t < TT; t++) {
        // prefetch this step's input gates (coalesced)
        float gx[8];
        #pragma unroll
        for (int r = 0; r < 8; r++)
            gx[r] = g_gates[((size_t)(b0r + r) * TT + t) * G3 + tid];

        // gh[r][tid] = Whh[tid] . h[r]   (packed f32x2)
        ull acc[8];
        #pragma unroll
        for (int r = 0; r < 8; r++) acc[r] = 0ull;
        #pragma unroll 8
        for (int kc = 0; kc < 32; kc++) {
            ulonglong2 w = W2[kc * 384 + tid];
            #pragma unroll
            for (int r = 0; r < 8; r++) {
                ulonglong2 h = h2[r * 32 + kc];
                fma2(acc[r], w.x, h.x);
                fma2(acc[r], w.y, h.y);
            }
        }

        #pragma unroll
        for (int r = 0; r < 8; r++) {
            float gh = pairsum(acc[r]) + bhh_j;
            if (sec == 0) {
                float pre = gx[r] + gh;
                As[r * 128 + jj] = 1.f / (1.f + expf(-pre));
            } else if (sec == 1) {
                float pre = gx[r] + gh;
                Bs[r * 128 + jj] = 1.f / (1.f + expf(-pre));
            } else {
                Cs[r * 128 + jj] = gh;
                Ds[r * 128 + jj] = gx[r];
            }
        }
        __syncthreads();

        // h_new = (1-z)*tanh(gxn + r*ghn) + z*h
        for (int i = tid; i < 1024; i += 384) {
            float rv = As[i], zv = Bs[i];
            float n  = tanhf(Ds[i] + rv * Cs[i]);
            hs[i] = (1.f - zv) * n + zv * hs[i];
        }
        __syncthreads();

        // logits + sigmoid, one warp per row
        if (warp < 8) {
            float s = 0.f;
            #pragma unroll
            for (int m = 0; m < 4; m++)
                s = fmaf(hs[warp * 128 + lane + m * 32], Wys[lane + m * 32], s);
            s += __shfl_down_sync(0xffffffffu, s, 16);
            s += __shfl_down_sync(0xffffffffu, s, 8);
            s += __shfl_down_sync(0xffffffffu, s, 4);
            s += __shfl_down_sync(0xffffffffu, s, 2);
            s += __shfl_down_sync(0xffffffffu, s, 1);
            if (lane == 0) {
                float logit = s + by0;
                size_t o = ((size_t)(b0r + warp) * TT + t) * 2;
                out[o]     = logit;
                out[o + 1] = 1.f / (1.f + expf(-logit));
            }
        }
    }
}

// ============================================================================
extern "C" void kernel_launch(void* const* d_in, const int* in_sizes, int n_in,
                              void* d_out, int out_size) {
    const float* x   = (const float*)d_in[0];
    const int*   a   = (const int*)  d_in[1];
    const int*   t   = (const int*)  d_in[2];
    const float* y   = (const float*)d_in[3];
    const float* eps = (const float*)d_in[5];
    const float* Wx  = (const float*)d_in[6];
    const float* bx  = (const float*)d_in[7];
    const float* Ea  = (const float*)d_in[8];
    const float* Et  = (const float*)d_in[9];
    const float* Wih = (const float*)d_in[10];
    const float* Whh = (const float*)d_in[11];
    const float* bih = (const float*)d_in[12];
    const float* bhh = (const float*)d_in[13];
    const float* W0  = (const float*)d_in[14];
    const float* b0  = (const float*)d_in[15];
    const float* Wy  = (const float*)d_in[16];
    const float* by  = (const float*)d_in[17];
    float* out = (float*)d_out;

    cudaFuncSetAttribute(k_gates, cudaFuncAttributeMaxDynamicSharedMemorySize, K2_SMEM);
    cudaFuncSetAttribute(k_rnn,   cudaFuncAttributeMaxDynamicSharedMemorySize, K3_SMEM);

    k_enc<<<BB, 128>>>(x, Wx, bx, eps, W0, b0);

    dim3 g2(6, BB * TT / 128);
    k_gates<<<g2, 256, K2_SMEM>>>(a, t, y, eps, Ea, Et, Wih, bih);

    k_rnn<<<BB / 8, 384, K3_SMEM>>>(Whh, bhh, Wy, by, out);
}

// round 4
// speedup vs baseline: 1.1410x; 1.0223x over previous
#include <cuda_runtime.h>
#include <math.h>

#define BB   1024
#define TT   256
#define DH   128
#define G3   384
#define DIN  129
#define DX   64
#define DEPS 16

typedef unsigned long long ull;

// packed fp32x2 FMA: d = a*b + d (elementwise on two packed floats)
__device__ __forceinline__ void fma2(ull& d, ull a, ull b) {
    asm("fma.rn.f32x2 %0, %1, %2, %0;" : "+l"(d) : "l"(a), "l"(b));
}
__device__ __forceinline__ float pairsum(ull v) {
    float lo, hi;
    asm("mov.b64 {%0, %1}, %2;" : "=f"(lo), "=f"(hi) : "l"(v));
    return lo + hi;
}

// ---- scratch (device globals: no runtime allocation allowed) ----
__device__ float g_xenc[BB * DX];
__device__ float g_h0[BB * DH];
__device__ float g_gates[(size_t)BB * TT * G3];   // 402 MB

// ============================================================================
// K1: x_enc = x @ Wx^T + bx ; h0 = tanh([x_enc, eps[:,0,:]] @ W0^T + b0)
// ============================================================================
__global__ void k_enc(const float* __restrict__ x,  const float* __restrict__ Wx,
                      const float* __restrict__ bx, const float* __restrict__ eps,
                      const float* __restrict__ W0, const float* __restrict__ b0) {
    __shared__ float xs[64], xe[64], e0[16];
    int b = blockIdx.x, tid = threadIdx.x;
    if (tid < 64)                 xs[tid]      = x[b * 64 + tid];
    if (tid >= 64 && tid < 80)    e0[tid - 64] = eps[(size_t)b * TT * DEPS + (tid - 64)];
    __syncthreads();
    if (tid < 64) {
        float acc = bx[tid];
        #pragma unroll
        for (int k = 0; k < 64; k++) acc = fmaf(Wx[tid * 64 + k], xs[k], acc);
        xe[tid] = acc;
        g_xenc[b * 64 + tid] = acc;
    }
    __syncthreads();
    float acc = b0[tid];
    #pragma unroll
    for (int k = 0; k < 64; k++) acc = fmaf(W0[tid * 80 + k], xe[k], acc);
    #pragma unroll
    for (int k = 0; k < 16; k++) acc = fmaf(W0[tid * 80 + 64 + k], e0[k], acc);
    g_h0[b * DH + tid] = tanhf(acc);
}

// ============================================================================
// K2: gates_x = inp @ Wih^T + bih   (f32x2 packed along K) — FMA-bound already
// block tile: 128 rows x 64 gates, 256 threads, 8x4 packed micro-tile
// ============================================================================
#define K2_SMEM ((128 * 132 + 65 * 64 * 2) * 4)

__global__ void k_gates(const int* __restrict__ a, const int* __restrict__ tt,
                        const float* __restrict__ y, const float* __restrict__ eps,
                        const float* __restrict__ Ea, const float* __restrict__ Et,
                        const float* __restrict__ Wih, const float* __restrict__ bih) {
    extern __shared__ float sm[];
    float* inp = sm;                 // [128][132] (k 129..131 zero-padded)
    float* Wt  = sm + 128 * 132;     // k-pairs: Wt[(kp*64+g)*2 + {0,1}]

    int tid  = threadIdx.x;
    int g0   = blockIdx.x * 64;
    int row0 = blockIdx.y * 128;

    for (int idx = tid; idx < 64 * 65; idx += 256) {
        int g = idx / 65, kp = idx - g * 65;
        const float* wrow = &Wih[(g0 + g) * 129];
        float w0 = wrow[2 * kp];
        float w1 = (2 * kp + 1 < 129) ? wrow[2 * kp + 1] : 0.f;
        Wt[(kp * 64 + g) * 2]     = w0;
        Wt[(kp * 64 + g) * 2 + 1] = w1;
    }
    for (int idx = tid; idx < 128 * 132; idx += 256) {
        int r = idx / 132, k = idx - r * 132;
        int rowg = row0 + r;
        int b = rowg >> 8, s = rowg & 255;
        float v;
        if      (k < 32)  v = Ea[a[b * TT + s] * 32 + k];
        else if (k < 48)  v = Et[tt[b * TT + s] * 16 + (k - 32)];
        else if (k < 112) v = g_xenc[b * 64 + (k - 48)];
        else if (k < 128) v = eps[((size_t)(b * TT + s)) * DEPS + (k - 112)];
        else if (k == 128) v = (s == 0) ? 0.f : y[b * TT + s - 1];
        else              v = 0.f;
        inp[r * 132 + k] = v;
    }
    __syncthreads();

    int tx = tid & 15, ty = tid >> 4;
    ull acc[8][4];
    #pragma unroll
    for (int i = 0; i < 8; i++)
        #pragma unroll
        for (int j = 0; j < 4; j++) acc[i][j] = 0ull;

    const float* wbase = &Wt[tx * 4 * 2];
    #pragma unroll 5
    for (int kp = 0; kp < 65; kp++) {
        ulonglong2 w01 = *(const ulonglong2*)&wbase[kp * 128];
        ulonglong2 w23 = *(const ulonglong2*)&wbase[kp * 128 + 4];
        #pragma unroll
        for (int i = 0; i < 8; i++) {
            ull av = *(const ull*)&inp[(ty * 8 + i) * 132 + 2 * kp];
            fma2(acc[i][0], av, w01.x);
            fma2(acc[i][1], av, w01.y);
            fma2(acc[i][2], av, w23.x);
            fma2(acc[i][3], av, w23.y);
        }
    }

    int gbase = g0 + tx * 4;
    float4 bi = *(const float4*)&bih[gbase];
    #pragma unroll
    for (int i = 0; i < 8; i++) {
        size_t off = (size_t)(row0 + ty * 8 + i) * G3 + gbase;
        float4 o = make_float4(pairsum(acc[i][0]) + bi.x,
                               pairsum(acc[i][1]) + bi.y,
                               pairsum(acc[i][2]) + bi.z,
                               pairsum(acc[i][3]) + bi.w);
        *(float4*)&g_gates[off] = o;
    }
}

// ============================================================================
// K3: GRU scan. Whh row of each gate-unit lives in REGISTERS (128 regs/thread)
// for all 256 steps; SMEM holds only h + gate-exchange buffers (21 KB).
// Per-step LDS = broadcast h reads only -> balanced with FMA pipe.
// ============================================================================
__global__ void __launch_bounds__(384, 1)
k_rnn(const float* __restrict__ Whh, const float* __restrict__ bhh,
      const float* __restrict__ Wy,  const float* __restrict__ by,
      float* __restrict__ out) {
    __shared__ __align__(16) float hs[8 * 128];
    __shared__ float As[8 * 128], Bs[8 * 128], Cs[8 * 128], Ds[8 * 128];
    __shared__ float Wys[128];
    const ulonglong2* hp = (const ulonglong2*)hs;   // [8][32] 16B chunks

    int tid = threadIdx.x;
    int b0r = blockIdx.x * 8;

    // Whh row 'tid' -> 32 x 16B register chunks (one-time global load)
    ulonglong2 wq[32];
    const ulonglong2* wrow = (const ulonglong2*)&Whh[tid * 128];
    #pragma unroll
    for (int kc = 0; kc < 32; kc++) wq[kc] = wrow[kc];

    for (int i = tid; i < 1024; i += 384) hs[i] = g_h0[b0r * DH + i];
    if (tid < 128) Wys[tid] = Wy[tid];
    float bhh_j = bhh[tid];
    float by0   = by[0];
    __syncthreads();

    int sec = tid >> 7, jj = tid & 127;
    int warp = tid >> 5, lane = tid & 31;

    for (int t = 0; t < TT; t++) {
        // prefetch this step's input gates (coalesced)
        float gx[8];
        #pragma unroll
        for (int r = 0; r < 8; r++)
            gx[r] = g_gates[((size_t)(b0r + r) * TT + t) * G3 + tid];

        // gh[r][tid] = Whh[tid] . h[r]   (W in regs, h via broadcast LDS.128)
        ull acc[8];
        #pragma unroll
        for (int r = 0; r < 8; r++) acc[r] = 0ull;
        #pragma unroll
        for (int kc = 0; kc < 32; kc++) {
            #pragma unroll
            for (int r = 0; r < 8; r++) {
                ulonglong2 h = hp[r * 32 + kc];
                fma2(acc[r], wq[kc].x, h.x);
                fma2(acc[r], wq[kc].y, h.y);
            }
        }

        #pragma unroll
        for (int r = 0; r < 8; r++) {
            float gh = pairsum(acc[r]) + bhh_j;
            if (sec == 0) {
                float pre = gx[r] + gh;
                As[r * 128 + jj] = 1.f / (1.f + expf(-pre));
            } else if (sec == 1) {
                float pre = gx[r] + gh;
                Bs[r * 128 + jj] = 1.f / (1.f + expf(-pre));
            } else {
                Cs[r * 128 + jj] = gh;
                Ds[r * 128 + jj] = gx[r];
            }
        }
        __syncthreads();

        // h_new = (1-z)*tanh(gxn + r*ghn) + z*h
        for (int i = tid; i < 1024; i += 384) {
            float rv = As[i], zv = Bs[i];
            float n  = tanhf(Ds[i] + rv * Cs[i]);
            hs[i] = (1.f - zv) * n + zv * hs[i];
        }
        __syncthreads();

        // logits + sigmoid, one warp per row
        if (warp < 8) {
            float s = 0.f;
            #pragma unroll
            for (int m = 0; m < 4; m++)
                s = fmaf(hs[warp * 128 + lane + m * 32], Wys[lane + m * 32], s);
            s += __shfl_down_sync(0xffffffffu, s, 16);
            s += __shfl_down_sync(0xffffffffu, s, 8);
            s += __shfl_down_sync(0xffffffffu, s, 4);
            s += __shfl_down_sync(0xffffffffu, s, 2);
            s += __shfl_down_sync(0xffffffffu, s, 1);
            if (lane == 0) {
                float logit = s + by0;
                size_t o = ((size_t)(b0r + warp) * TT + t) * 2;
                out[o]     = logit;
                out[o + 1] = 1.f / (1.f + expf(-logit));
            }
        }
    }
}

// ============================================================================
extern "C" void kernel_launch(void* const* d_in, const int* in_sizes, int n_in,
                              void* d_out, int out_size) {
    const float* x   = (const float*)d_in[0];
    const int*   a   = (const int*)  d_in[1];
    const int*   t   = (const int*)  d_in[2];
    const float* y   = (const float*)d_in[3];
    const float* eps = (const float*)d_in[5];
    const float* Wx  = (const float*)d_in[6];
    const float* bx  = (const float*)d_in[7];
    const float* Ea  = (const float*)d_in[8];
    const float* Et  = (const float*)d_in[9];
    const float* Wih = (const float*)d_in[10];
    const float* Whh = (const float*)d_in[11];
    const float* bih = (const float*)d_in[12];
    const float* bhh = (const float*)d_in[13];
    const float* W0  = (const float*)d_in[14];
    const float* b0  = (const float*)d_in[15];
    const float* Wy  = (const float*)d_in[16];
    const float* by  = (const float*)d_in[17];
    float* out = (float*)d_out;

    cudaFuncSetAttribute(k_gates, cudaFuncAttributeMaxDynamicSharedMemorySize, K2_SMEM);

    k_enc<<<BB, 128>>>(x, Wx, bx, eps, W0, b0);

    dim3 g2(6, BB * TT / 128);
    k_gates<<<g2, 256, K2_SMEM>>>(a, t, y, eps, Ea, Et, Wih, bih);

    k_rnn<<<BB / 8, 384>>>(Whh, bhh, Wy, by, out);
}

// round 5
// speedup vs baseline: 1.4325x; 1.2555x over previous
#include <cuda_runtime.h>
#include <cuda_bf16.h>
#include <math.h>

#define BB   1024
#define TT   256
#define DH   128
#define G3   384
#define DX   64
#define DEPS 16
#define KPAD 152          // padded K stride (bank-conflict-free, 144 used)
#define KCH  9            // ceil(129/16) k-chunks

typedef unsigned long long ull;

__device__ __forceinline__ void fma2(ull& d, ull a, ull b) {
    asm("fma.rn.f32x2 %0, %1, %2, %0;" : "+l"(d) : "l"(a), "l"(b));
}
__device__ __forceinline__ float pairsum(ull v) {
    float lo, hi;
    asm("mov.b64 {%0, %1}, %2;" : "=f"(lo), "=f"(hi) : "l"(v));
    return lo + hi;
}

// mma.sync m16n8k16 bf16 -> fp32
__device__ __forceinline__ void mma16816(float* c, const unsigned* a, const unsigned* b) {
    asm volatile(
        "mma.sync.aligned.m16n8k16.row.col.f32.bf16.bf16.f32 "
        "{%0,%1,%2,%3}, {%4,%5,%6,%7}, {%8,%9}, {%0,%1,%2,%3};"
        : "+f"(c[0]), "+f"(c[1]), "+f"(c[2]), "+f"(c[3])
        : "r"(a[0]), "r"(a[1]), "r"(a[2]), "r"(a[3]), "r"(b[0]), "r"(b[1]));
}

// ---- scratch ----
__device__ float g_xenc[BB * DX];
__device__ float g_h0[BB * DH];
__device__ float g_gates[(size_t)BB * TT * G3];          // 402 MB
__device__ __nv_bfloat16 g_Whi[G3 * KPAD];
__device__ __nv_bfloat16 g_Wlo[G3 * KPAD];

// ============================================================================
// K1: x_enc = x @ Wx^T + bx ; h0 = tanh([x_enc, eps0] @ W0^T + b0)
// ============================================================================
__global__ void k_enc(const float* __restrict__ x,  const float* __restrict__ Wx,
                      const float* __restrict__ bx, const float* __restrict__ eps,
                      const float* __restrict__ W0, const float* __restrict__ b0) {
    __shared__ float xs[64], xe[64], e0[16];
    int b = blockIdx.x, tid = threadIdx.x;
    if (tid < 64)                 xs[tid]      = x[b * 64 + tid];
    if (tid >= 64 && tid < 80)    e0[tid - 64] = eps[(size_t)b * TT * DEPS + (tid - 64)];
    __syncthreads();
    if (tid < 64) {
        float acc = bx[tid];
        #pragma unroll
        for (int k = 0; k < 64; k++) acc = fmaf(Wx[tid * 64 + k], xs[k], acc);
        xe[tid] = acc;
        g_xenc[b * 64 + tid] = acc;
    }
    __syncthreads();
    float acc = b0[tid];
    #pragma unroll
    for (int k = 0; k < 64; k++) acc = fmaf(W0[tid * 80 + k], xe[k], acc);
    #pragma unroll
    for (int k = 0; k < 16; k++) acc = fmaf(W0[tid * 80 + 64 + k], e0[k], acc);
    g_h0[b * DH + tid] = tanhf(acc);
}

// ============================================================================
// K1b: split Wih into bf16 hi/lo with zero-padded K stride
// ============================================================================
__global__ void k_wsplit(const float* __restrict__ Wih) {
    int g = blockIdx.x, k = threadIdx.x;            // 384 blocks x 152 threads
    float v = (k < 129) ? Wih[g * 129 + k] : 0.f;
    __nv_bfloat16 hi = __float2bfloat16(v);
    __nv_bfloat16 lo = __float2bfloat16(v - __bfloat162float(hi));
    g_Whi[g * KPAD + k] = hi;
    g_Wlo[g * KPAD + k] = lo;
}

// ============================================================================
// K2: gates_x = inp @ Wih^T + bih via mma.sync bf16 (split hi/lo, 3 MMAs)
// block tile 128 rows x 128 gates x K144, 256 thr (8 warps = 4m x 2n)
// ============================================================================
#define K2_SMEM (4 * 128 * KPAD * 2)     // sAhi,sAlo,sWhi,sWlo

__global__ void __launch_bounds__(256, 1)
k_gates(const int* __restrict__ a, const int* __restrict__ tt,
        const float* __restrict__ y, const float* __restrict__ eps,
        const float* __restrict__ Ea, const float* __restrict__ Et,
        const float* __restrict__ bih) {
    extern __shared__ __nv_bfloat16 smb[];
    __nv_bfloat16* sAhi = smb;
    __nv_bfloat16* sAlo = smb + 128 * KPAD;
    __nv_bfloat16* sWhi = smb + 2 * 128 * KPAD;
    __nv_bfloat16* sWlo = smb + 3 * 128 * KPAD;

    int tid  = threadIdx.x;
    int g0   = blockIdx.x * 128;
    int row0 = blockIdx.y * 128;

    // ---- stage W tiles (pre-split bf16, 16B copies) ----
    {
        const uint4* srch = (const uint4*)&g_Whi[g0 * KPAD];
        const uint4* srcl = (const uint4*)&g_Wlo[g0 * KPAD];
        uint4* dsth = (uint4*)sWhi;
        uint4* dstl = (uint4*)sWlo;
        #pragma unroll
        for (int i = tid; i < 128 * KPAD / 8; i += 256) {
            dsth[i] = srch[i];
            dstl[i] = srcl[i];
        }
    }
    // ---- gather + split input rows: pairs (k0 even) ----
    for (int p = tid; p < 128 * (KPAD / 2); p += 256) {
        int r = p / (KPAD / 2), kp = p - r * (KPAD / 2);
        int k0 = 2 * kp;
        int rowg = row0 + r;
        int b = rowg >> 8, s = rowg & 255;
        float v0, v1;
        if (k0 < 32) {
            int ai = a[b * TT + s] * 32 + k0;
            v0 = Ea[ai]; v1 = Ea[ai + 1];
        } else if (k0 < 48) {
            int ti = tt[b * TT + s] * 16 + (k0 - 32);
            v0 = Et[ti]; v1 = Et[ti + 1];
        } else if (k0 < 112) {
            const float* xp = &g_xenc[b * 64 + (k0 - 48)];
            v0 = xp[0]; v1 = xp[1];
        } else if (k0 < 128) {
            const float* ep = &eps[((size_t)(b * TT + s)) * DEPS + (k0 - 112)];
            v0 = ep[0]; v1 = ep[1];
        } else if (k0 == 128) {
            v0 = (s == 0) ? 0.f : y[b * TT + s - 1];
            v1 = 0.f;
        } else {
            v0 = 0.f; v1 = 0.f;
        }
        __nv_bfloat16 h0 = __float2bfloat16(v0), h1 = __float2bfloat16(v1);
        float l0f = v0 - __bfloat162float(h0), l1f = v1 - __bfloat162float(h1);
        __nv_bfloat162 hp; hp.x = h0; hp.y = h1;
        __nv_bfloat162 lp; lp.x = __float2bfloat16(l0f); lp.y = __float2bfloat16(l1f);
        *(__nv_bfloat162*)&sAhi[r * KPAD + k0] = hp;
        *(__nv_bfloat162*)&sAlo[r * KPAD + k0] = lp;
    }
    __syncthreads();

    // ---- MMA mainloop ----
    int warp = tid >> 5, lane = tid & 31;
    int grp = lane >> 2, q = lane & 3;          // groupID, tid4
    int m_base = (warp >> 1) * 32;              // 4 m-warps x 32 rows
    int n_base = (warp & 1) * 64;               // 2 n-warps x 64 gates

    float c[2][8][4];
    #pragma unroll
    for (int m = 0; m < 2; m++)
        #pragma unroll
        for (int n = 0; n < 8; n++)
            #pragma unroll
            for (int i = 0; i < 4; i++) c[m][n][i] = 0.f;

    #pragma unroll
    for (int kc = 0; kc < KCH; kc++) {
        int k0 = kc * 16 + q * 2;
        unsigned ahi[2][4], alo[2][4];
        #pragma unroll
        for (int m = 0; m < 2; m++) {
            int r = m_base + m * 16 + grp;
            ahi[m][0] = *(const unsigned*)&sAhi[r * KPAD + k0];
            ahi[m][1] = *(const unsigned*)&sAhi[(r + 8) * KPAD + k0];
            ahi[m][2] = *(const unsigned*)&sAhi[r * KPAD + k0 + 8];
            ahi[m][3] = *(const unsigned*)&sAhi[(r + 8) * KPAD + k0 + 8];
            alo[m][0] = *(const unsigned*)&sAlo[r * KPAD + k0];
            alo[m][1] = *(const unsigned*)&sAlo[(r + 8) * KPAD + k0];
            alo[m][2] = *(const unsigned*)&sAlo[r * KPAD + k0 + 8];
            alo[m][3] = *(const unsigned*)&sAlo[(r + 8) * KPAD + k0 + 8];
        }
        #pragma unroll
        for (int n = 0; n < 8; n++) {
            int g = n_base + n * 8 + grp;
            unsigned bhi[2], blo[2];
            bhi[0] = *(const unsigned*)&sWhi[g * KPAD + k0];
            bhi[1] = *(const unsigned*)&sWhi[g * KPAD + k0 + 8];
            blo[0] = *(const unsigned*)&sWlo[g * KPAD + k0];
            blo[1] = *(const unsigned*)&sWlo[g * KPAD + k0 + 8];
            #pragma unroll
            for (int m = 0; m < 2; m++) {
                mma16816(c[m][n], ahi[m], bhi);
                mma16816(c[m][n], ahi[m], blo);
                mma16816(c[m][n], alo[m], bhi);
            }
        }
    }

    // ---- epilogue: +bih, store fp32 ----
    #pragma unroll
    for (int n = 0; n < 8; n++) {
        int col = g0 + n_base + n * 8 + q * 2;
        float2 bv = *(const float2*)&bih[col];
        #pragma unroll
        for (int m = 0; m < 2; m++) {
            int r = row0 + m_base + m * 16 + grp;
            float2 o0 = make_float2(c[m][n][0] + bv.x, c[m][n][1] + bv.y);
            float2 o1 = make_float2(c[m][n][2] + bv.x, c[m][n][3] + bv.y);
            *(float2*)&g_gates[(size_t)r * G3 + col]       = o0;
            *(float2*)&g_gates[(size_t)(r + 8) * G3 + col] = o1;
        }
    }
}

// ============================================================================
// K3: GRU scan (unchanged from R4): W in registers, h broadcast via SMEM
// ============================================================================
__global__ void __launch_bounds__(384, 1)
k_rnn(const float* __restrict__ Whh, const float* __restrict__ bhh,
      const float* __restrict__ Wy,  const float* __restrict__ by,
      float* __restrict__ out) {
    __shared__ __align__(16) float hs[8 * 128];
    __shared__ float As[8 * 128], Bs[8 * 128], Cs[8 * 128], Ds[8 * 128];
    __shared__ float Wys[128];
    const ulonglong2* hp = (const ulonglong2*)hs;

    int tid = threadIdx.x;
    int b0r = blockIdx.x * 8;

    ulonglong2 wq[32];
    const ulonglong2* wrow = (const ulonglong2*)&Whh[tid * 128];
    #pragma unroll
    for (int kc = 0; kc < 32; kc++) wq[kc] = wrow[kc];

    for (int i = tid; i < 1024; i += 384) hs[i] = g_h0[b0r * DH + i];
    if (tid < 128) Wys[tid] = Wy[tid];
    float bhh_j = bhh[tid];
    float by0   = by[0];
    __syncthreads();

    int sec = tid >> 7, jj = tid & 127;
    int warp = tid >> 5, lane = tid & 31;

    for (int t = 0; t < TT; t++) {
        float gx[8];
        #pragma unroll
        for (int r = 0; r < 8; r++)
            gx[r] = g_gates[((size_t)(b0r + r) * TT + t) * G3 + tid];

        ull acc[8];
        #pragma unroll
        for (int r = 0; r < 8; r++) acc[r] = 0ull;
        #pragma unroll
        for (int kc = 0; kc < 32; kc++) {
            #pragma unroll
            for (int r = 0; r < 8; r++) {
                ulonglong2 h = hp[r * 32 + kc];
                fma2(acc[r], wq[kc].x, h.x);
                fma2(acc[r], wq[kc].y, h.y);
            }
        }

        #pragma unroll
        for (int r = 0; r < 8; r++) {
            float gh = pairsum(acc[r]) + bhh_j;
            if (sec == 0) {
                As[r * 128 + jj] = 1.f / (1.f + expf(-(gx[r] + gh)));
            } else if (sec == 1) {
                Bs[r * 128 + jj] = 1.f / (1.f + expf(-(gx[r] + gh)));
            } else {
                Cs[r * 128 + jj] = gh;
                Ds[r * 128 + jj] = gx[r];
            }
        }
        __syncthreads();

        for (int i = tid; i < 1024; i += 384) {
            float rv = As[i], zv = Bs[i];
            float n  = tanhf(Ds[i] + rv * Cs[i]);
            hs[i] = (1.f - zv) * n + zv * hs[i];
        }
        __syncthreads();

        if (warp < 8) {
            float s = 0.f;
            #pragma unroll
            for (int m = 0; m < 4; m++)
                s = fmaf(hs[warp * 128 + lane + m * 32], Wys[lane + m * 32], s);
            s += __shfl_down_sync(0xffffffffu, s, 16);
            s += __shfl_down_sync(0xffffffffu, s, 8);
            s += __shfl_down_sync(0xffffffffu, s, 4);
            s += __shfl_down_sync(0xffffffffu, s, 2);
            s += __shfl_down_sync(0xffffffffu, s, 1);
            if (lane == 0) {
                float logit = s + by0;
                size_t o = ((size_t)(b0r + warp) * TT + t) * 2;
                out[o]     = logit;
                out[o + 1] = 1.f / (1.f + expf(-logit));
            }
        }
    }
}

// ============================================================================
extern "C" void kernel_launch(void* const* d_in, const int* in_sizes, int n_in,
                              void* d_out, int out_size) {
    const float* x   = (const float*)d_in[0];
    const int*   a   = (const int*)  d_in[1];
    const int*   t   = (const int*)  d_in[2];
    const float* y   = (const float*)d_in[3];
    const float* eps = (const float*)d_in[5];
    const float* Wx  = (const float*)d_in[6];
    const float* bx  = (const float*)d_in[7];
    const float* Ea  = (const float*)d_in[8];
    const float* Et  = (const float*)d_in[9];
    const float* Wih = (const float*)d_in[10];
    const float* Whh = (const float*)d_in[11];
    const float* bih = (const float*)d_in[12];
    const float* bhh = (const float*)d_in[13];
    const float* W0  = (const float*)d_in[14];
    const float* b0  = (const float*)d_in[15];
    const float* Wy  = (const float*)d_in[16];
    const float* by  = (const float*)d_in[17];
    float* out = (float*)d_out;

    cudaFuncSetAttribute(k_gates, cudaFuncAttributeMaxDynamicSharedMemorySize, K2_SMEM);

    k_enc<<<BB, 128>>>(x, Wx, bx, eps, W0, b0);
    k_wsplit<<<G3, KPAD>>>(Wih);

    dim3 g2(3, BB * TT / 128);
    k_gates<<<g2, 256, K2_SMEM>>>(a, t, y, eps, Ea, Et, bih);

    k_rnn<<<BB / 8, 384>>>(Whh, bhh, Wy, by, out);
}

// round 6
// speedup vs baseline: 2.0325x; 1.4189x over previous
#include <cuda_runtime.h>
#include <cuda_bf16.h>
#include <math.h>

#define BB   1024
#define TT   256
#define DH   128
#define G3   384
#define DX   64
#define DEPS 16
#define KPAD 152
#define KCH  9
#define GH_S 388    // Gh row stride (fp32 words) -> conflict-free MMA scatter
#define HB_S 136    // h bf16 row stride -> conflict-free b-frag loads

// mma.sync m16n8k16 bf16 -> fp32
__device__ __forceinline__ void mma16816(float* c, const unsigned* a, const unsigned* b) {
    asm volatile(
        "mma.sync.aligned.m16n8k16.row.col.f32.bf16.bf16.f32 "
        "{%0,%1,%2,%3}, {%4,%5,%6,%7}, {%8,%9}, {%0,%1,%2,%3};"
        : "+f"(c[0]), "+f"(c[1]), "+f"(c[2]), "+f"(c[3])
        : "r"(a[0]), "r"(a[1]), "r"(a[2]), "r"(a[3]), "r"(b[0]), "r"(b[1]));
}
__device__ __forceinline__ unsigned bfsplit_hi(float x, float y) {
    __nv_bfloat162 p; p.x = __float2bfloat16(x); p.y = __float2bfloat16(y);
    return *(unsigned*)&p;
}
__device__ __forceinline__ unsigned bfsplit_lo(float x, float y) {
    __nv_bfloat162 p;
    p.x = __float2bfloat16(x - __bfloat162float(__float2bfloat16(x)));
    p.y = __float2bfloat16(y - __bfloat162float(__float2bfloat16(y)));
    return *(unsigned*)&p;
}

// ---- scratch ----
__device__ float g_xenc[BB * DX];
__device__ float g_h0[BB * DH];
__device__ float g_gates[(size_t)BB * TT * G3];
__device__ __nv_bfloat16 g_Whi[G3 * KPAD];
__device__ __nv_bfloat16 g_Wlo[G3 * KPAD];

// ============================================================================
// K1: x_enc + h0
// ============================================================================
__global__ void k_enc(const float* __restrict__ x,  const float* __restrict__ Wx,
                      const float* __restrict__ bx, const float* __restrict__ eps,
                      const float* __restrict__ W0, const float* __restrict__ b0) {
    __shared__ float xs[64], xe[64], e0[16];
    int b = blockIdx.x, tid = threadIdx.x;
    if (tid < 64)                 xs[tid]      = x[b * 64 + tid];
    if (tid >= 64 && tid < 80)    e0[tid - 64] = eps[(size_t)b * TT * DEPS + (tid - 64)];
    __syncthreads();
    if (tid < 64) {
        float acc = bx[tid];
        #pragma unroll
        for (int k = 0; k < 64; k++) acc = fmaf(Wx[tid * 64 + k], xs[k], acc);
        xe[tid] = acc;
        g_xenc[b * 64 + tid] = acc;
    }
    __syncthreads();
    float acc = b0[tid];
    #pragma unroll
    for (int k = 0; k < 64; k++) acc = fmaf(W0[tid * 80 + k], xe[k], acc);
    #pragma unroll
    for (int k = 0; k < 16; k++) acc = fmaf(W0[tid * 80 + 64 + k], e0[k], acc);
    g_h0[b * DH + tid] = tanhf(acc);
}

// ============================================================================
// K1b: split Wih into bf16 hi/lo
// ============================================================================
__global__ void k_wsplit(const float* __restrict__ Wih) {
    int g = blockIdx.x, k = threadIdx.x;
    float v = (k < 129) ? Wih[g * 129 + k] : 0.f;
    __nv_bfloat16 hi = __float2bfloat16(v);
    __nv_bfloat16 lo = __float2bfloat16(v - __bfloat162float(hi));
    g_Whi[g * KPAD + k] = hi;
    g_Wlo[g * KPAD + k] = lo;
}

// ============================================================================
// K2: gates GEMM via split-bf16 mma (unchanged from R5)
// ============================================================================
#define K2_SMEM (4 * 128 * KPAD * 2)

__global__ void __launch_bounds__(256, 1)
k_gates(const int* __restrict__ a, const int* __restrict__ tt,
        const float* __restrict__ y, const float* __restrict__ eps,
        const float* __restrict__ Ea, const float* __restrict__ Et,
        const float* __restrict__ bih) {
    extern __shared__ __nv_bfloat16 smb[];
    __nv_bfloat16* sAhi = smb;
    __nv_bfloat16* sAlo = smb + 128 * KPAD;
    __nv_bfloat16* sWhi = smb + 2 * 128 * KPAD;
    __nv_bfloat16* sWlo = smb + 3 * 128 * KPAD;

    int tid  = threadIdx.x;
    int g0   = blockIdx.x * 128;
    int row0 = blockIdx.y * 128;

    {
        const uint4* srch = (const uint4*)&g_Whi[g0 * KPAD];
        const uint4* srcl = (const uint4*)&g_Wlo[g0 * KPAD];
        uint4* dsth = (uint4*)sWhi;
        uint4* dstl = (uint4*)sWlo;
        #pragma unroll
        for (int i = tid; i < 128 * KPAD / 8; i += 256) {
            dsth[i] = srch[i];
            dstl[i] = srcl[i];
        }
    }
    for (int p = tid; p < 128 * (KPAD / 2); p += 256) {
        int r = p / (KPAD / 2), kp = p - r * (KPAD / 2);
        int k0 = 2 * kp;
        int rowg = row0 + r;
        int b = rowg >> 8, s = rowg & 255;
        float v0, v1;
        if (k0 < 32) {
            int ai = a[b * TT + s] * 32 + k0; v0 = Ea[ai]; v1 = Ea[ai + 1];
        } else if (k0 < 48) {
            int ti = tt[b * TT + s] * 16 + (k0 - 32); v0 = Et[ti]; v1 = Et[ti + 1];
        } else if (k0 < 112) {
            const float* xp = &g_xenc[b * 64 + (k0 - 48)]; v0 = xp[0]; v1 = xp[1];
        } else if (k0 < 128) {
            const float* ep = &eps[((size_t)(b * TT + s)) * DEPS + (k0 - 112)];
            v0 = ep[0]; v1 = ep[1];
        } else if (k0 == 128) {
            v0 = (s == 0) ? 0.f : y[b * TT + s - 1]; v1 = 0.f;
        } else { v0 = 0.f; v1 = 0.f; }
        *(unsigned*)&sAhi[r * KPAD + k0] = bfsplit_hi(v0, v1);
        *(unsigned*)&sAlo[r * KPAD + k0] = bfsplit_lo(v0, v1);
    }
    __syncthreads();

    int warp = tid >> 5, lane = tid & 31;
    int grp = lane >> 2, q = lane & 3;
    int m_base = (warp >> 1) * 32;
    int n_base = (warp & 1) * 64;

    float c[2][8][4];
    #pragma unroll
    for (int m = 0; m < 2; m++)
        #pragma unroll
        for (int n = 0; n < 8; n++)
            #pragma unroll
            for (int i = 0; i < 4; i++) c[m][n][i] = 0.f;

    #pragma unroll
    for (int kc = 0; kc < KCH; kc++) {
        int k0 = kc * 16 + q * 2;
        unsigned ahi[2][4], alo[2][4];
        #pragma unroll
        for (int m = 0; m < 2; m++) {
            int r = m_base + m * 16 + grp;
            ahi[m][0] = *(const unsigned*)&sAhi[r * KPAD + k0];
            ahi[m][1] = *(const unsigned*)&sAhi[(r + 8) * KPAD + k0];
            ahi[m][2] = *(const unsigned*)&sAhi[r * KPAD + k0 + 8];
            ahi[m][3] = *(const unsigned*)&sAhi[(r + 8) * KPAD + k0 + 8];
            alo[m][0] = *(const unsigned*)&sAlo[r * KPAD + k0];
            alo[m][1] = *(const unsigned*)&sAlo[(r + 8) * KPAD + k0];
            alo[m][2] = *(const unsigned*)&sAlo[r * KPAD + k0 + 8];
            alo[m][3] = *(const unsigned*)&sAlo[(r + 8) * KPAD + k0 + 8];
        }
        #pragma unroll
        for (int n = 0; n < 8; n++) {
            int g = n_base + n * 8 + grp;
            unsigned bhi[2], blo[2];
            bhi[0] = *(const unsigned*)&sWhi[g * KPAD + k0];
            bhi[1] = *(const unsigned*)&sWhi[g * KPAD + k0 + 8];
            blo[0] = *(const unsigned*)&sWlo[g * KPAD + k0];
            blo[1] = *(const unsigned*)&sWlo[g * KPAD + k0 + 8];
            #pragma unroll
            for (int m = 0; m < 2; m++) {
                mma16816(c[m][n], ahi[m], bhi);
                mma16816(c[m][n], ahi[m], blo);
                mma16816(c[m][n], alo[m], bhi);
            }
        }
    }

    #pragma unroll
    for (int n = 0; n < 8; n++) {
        int col = g0 + n_base + n * 8 + q * 2;
        float2 bv = *(const float2*)&bih[col];
        #pragma unroll
        for (int m = 0; m < 2; m++) {
            int r = row0 + m_base + m * 16 + grp;
            float2 o0 = make_float2(c[m][n][0] + bv.x, c[m][n][1] + bv.y);
            float2 o1 = make_float2(c[m][n][2] + bv.x, c[m][n][3] + bv.y);
            *(float2*)&g_gates[(size_t)r * G3 + col]       = o0;
            *(float2*)&g_gates[(size_t)(r + 8) * G3 + col] = o1;
        }
    }
}

// ============================================================================
// K3: GRU scan via tensor cores.
// gh[384 gates x 8 rows] = Whh @ h^T per step. A = Whh frags resident in
// registers (12 warps x 2 m-tiles); B = h re-split to bf16 hi/lo each step.
// ============================================================================
__global__ void __launch_bounds__(384, 1)
k_rnn(const float* __restrict__ Whh, const float* __restrict__ bhh,
      const float* __restrict__ Wy,  const float* __restrict__ by,
      float* __restrict__ out) {
    __shared__ __align__(16) float hs[1024];
    __shared__ float Gh[8 * GH_S];
    __shared__ float As[1024], Bs[1024], Cs[1024], Ds[1024];
    __shared__ float Wys[128];
    __shared__ __nv_bfloat16 hhi[8 * HB_S], hlo[8 * HB_S];

    int tid = threadIdx.x;
    int b0r = blockIdx.x * 8;
    int warp = tid >> 5, lane = tid & 31;
    int grp = lane >> 2, q = lane & 3;

    // preload Whh A-fragments (split bf16) -> registers, resident all 256 steps
    unsigned Ahi[2][8][4], Alo[2][8][4];
    #pragma unroll
    for (int mt = 0; mt < 2; mt++)
        #pragma unroll
        for (int kc = 0; kc < 8; kc++)
            #pragma unroll
            for (int i = 0; i < 4; i++) {
                int g = warp * 32 + mt * 16 + grp + ((i & 1) ? 8 : 0);
                int k = kc * 16 + 2 * q + ((i & 2) ? 8 : 0);
                float2 wv = *(const float2*)&Whh[g * 128 + k];
                Ahi[mt][kc][i] = bfsplit_hi(wv.x, wv.y);
                Alo[mt][kc][i] = bfsplit_lo(wv.x, wv.y);
            }

    for (int i = tid; i < 1024; i += 384) {
        float h = g_h0[b0r * DH + i];
        hs[i] = h;
        int r = i >> 7, k = i & 127;
        __nv_bfloat16 hi = __float2bfloat16(h);
        hhi[r * HB_S + k] = hi;
        hlo[r * HB_S + k] = __float2bfloat16(h - __bfloat162float(hi));
    }
    if (tid < 128) Wys[tid] = Wy[tid];
    float bhh_j = bhh[tid];
    float by0   = by[0];
    __syncthreads();

    int sec = tid >> 7, jj = tid & 127;

    for (int t = 0; t < TT; t++) {
        float gx[8];
        #pragma unroll
        for (int r = 0; r < 8; r++)
            gx[r] = g_gates[((size_t)(b0r + r) * TT + t) * G3 + tid];

        // MMA: gh = Whh @ h^T (split bf16, 3 products)
        float c0[4] = {0.f, 0.f, 0.f, 0.f}, c1[4] = {0.f, 0.f, 0.f, 0.f};
        #pragma unroll
        for (int kc = 0; kc < 8; kc++) {
            int koff = kc * 16 + 2 * q;
            unsigned bhi[2], blo[2];
            bhi[0] = *(const unsigned*)&hhi[grp * HB_S + koff];
            bhi[1] = *(const unsigned*)&hhi[grp * HB_S + koff + 8];
            blo[0] = *(const unsigned*)&hlo[grp * HB_S + koff];
            blo[1] = *(const unsigned*)&hlo[grp * HB_S + koff + 8];
            mma16816(c0, Ahi[0][kc], bhi);
            mma16816(c0, Alo[0][kc], bhi);
            mma16816(c0, Ahi[0][kc], blo);
            mma16816(c1, Ahi[1][kc], bhi);
            mma16816(c1, Alo[1][kc], bhi);
            mma16816(c1, Ahi[1][kc], blo);
        }
        // scatter C[m=gate][n=row] to Gh (stride 388: conflict-free)
        {
            int gsc = warp * 32 + grp;
            Gh[(2 * q)     * GH_S + gsc]      = c0[0];
            Gh[(2 * q + 1) * GH_S + gsc]      = c0[1];
            Gh[(2 * q)     * GH_S + gsc + 8]  = c0[2];
            Gh[(2 * q + 1) * GH_S + gsc + 8]  = c0[3];
            Gh[(2 * q)     * GH_S + gsc + 16] = c1[0];
            Gh[(2 * q + 1) * GH_S + gsc + 16] = c1[1];
            Gh[(2 * q)     * GH_S + gsc + 24] = c1[2];
            Gh[(2 * q + 1) * GH_S + gsc + 24] = c1[3];
        }
        __syncthreads();

        // gates: thread tid owns gate tid across 8 rows
        #pragma unroll
        for (int r = 0; r < 8; r++) {
            float gh = Gh[r * GH_S + tid] + bhh_j;
            if (sec == 0) {
                As[r * 128 + jj] = 1.f / (1.f + expf(-(gx[r] + gh)));
            } else if (sec == 1) {
                Bs[r * 128 + jj] = 1.f / (1.f + expf(-(gx[r] + gh)));
            } else {
                Cs[r * 128 + jj] = gh;
                Ds[r * 128 + jj] = gx[r];
            }
        }
        __syncthreads();

        // h update + re-split to bf16
        for (int i = tid; i < 1024; i += 384) {
            float rv = As[i], zv = Bs[i];
            float n  = tanhf(Ds[i] + rv * Cs[i]);
            float hn = (1.f - zv) * n + zv * hs[i];
            hs[i] = hn;
            int r = i >> 7, k = i & 127;
            __nv_bfloat16 hi = __float2bfloat16(hn);
            hhi[r * HB_S + k] = hi;
            hlo[r * HB_S + k] = __float2bfloat16(hn - __bfloat162float(hi));
        }
        __syncthreads();

        // output: logits + sigmoid, one warp per row
        if (warp < 8) {
            float s = 0.f;
            #pragma unroll
            for (int m = 0; m < 4; m++)
                s = fmaf(hs[warp * 128 + lane + m * 32], Wys[lane + m * 32], s);
            s += __shfl_down_sync(0xffffffffu, s, 16);
            s += __shfl_down_sync(0xffffffffu, s, 8);
            s += __shfl_down_sync(0xffffffffu, s, 4);
            s += __shfl_down_sync(0xffffffffu, s, 2);
            s += __shfl_down_sync(0xffffffffu, s, 1);
            if (lane == 0) {
                float logit = s + by0;
                size_t o = ((size_t)(b0r + warp) * TT + t) * 2;
                out[o]     = logit;
                out[o + 1] = 1.f / (1.f + expf(-logit));
            }
        }
    }
}

// ============================================================================
extern "C" void kernel_launch(void* const* d_in, const int* in_sizes, int n_in,
                              void* d_out, int out_size) {
    const float* x   = (const float*)d_in[0];
    const int*   a   = (const int*)  d_in[1];
    const int*   t   = (const int*)  d_in[2];
    const float* y   = (const float*)d_in[3];
    const float* eps = (const float*)d_in[5];
    const float* Wx  = (const float*)d_in[6];
    const float* bx  = (const float*)d_in[7];
    const float* Ea  = (const float*)d_in[8];
    const float* Et  = (const float*)d_in[9];
    const float* Wih = (const float*)d_in[10];
    const float* Whh = (const float*)d_in[11];
    const float* bih = (const float*)d_in[12];
    const float* bhh = (const float*)d_in[13];
    const float* W0  = (const float*)d_in[14];
    const float* b0  = (const float*)d_in[15];
    const float* Wy  = (const float*)d_in[16];
    const float* by  = (const float*)d_in[17];
    float* out = (float*)d_out;

    cudaFuncSetAttribute(k_gates, cudaFuncAttributeMaxDynamicSharedMemorySize, K2_SMEM);

    k_enc<<<BB, 128>>>(x, Wx, bx, eps, W0, b0);
    k_wsplit<<<G3, KPAD>>>(Wih);

    dim3 g2(3, BB * TT / 128);
    k_gates<<<g2, 256, K2_SMEM>>>(a, t, y, eps, Ea, Et, bih);

    k_rnn<<<BB / 8, 384>>>(Whh, bhh, Wy, by, out);
}

// round 7
// speedup vs baseline: 3.7404x; 1.8403x over previous
#include <cuda_runtime.h>
#include <cuda_bf16.h>
#include <math.h>

#define BB   1024
#define TT   256
#define DH   128
#define G3   384
#define DX   64
#define DEPS 16
#define GH_S 388    // Gh row stride (fp32 words) -> conflict-free MMA scatter
#define HB_S 136    // h bf16 row stride -> conflict-free b-frag loads
#define CH   64     // positions per k_gx block

// mma.sync m16n8k16 bf16 -> fp32
__device__ __forceinline__ void mma16816(float* c, const unsigned* a, const unsigned* b) {
    asm volatile(
        "mma.sync.aligned.m16n8k16.row.col.f32.bf16.bf16.f32 "
        "{%0,%1,%2,%3}, {%4,%5,%6,%7}, {%8,%9}, {%0,%1,%2,%3};"
        : "+f"(c[0]), "+f"(c[1]), "+f"(c[2]), "+f"(c[3])
        : "r"(a[0]), "r"(a[1]), "r"(a[2]), "r"(a[3]), "r"(b[0]), "r"(b[1]));
}
__device__ __forceinline__ unsigned bfsplit_hi(float x, float y) {
    __nv_bfloat162 p; p.x = __float2bfloat16(x); p.y = __float2bfloat16(y);
    return *(unsigned*)&p;
}
__device__ __forceinline__ unsigned bfsplit_lo(float x, float y) {
    __nv_bfloat162 p;
    p.x = __float2bfloat16(x - __bfloat162float(__float2bfloat16(x)));
    p.y = __float2bfloat16(y - __bfloat162float(__float2bfloat16(y)));
    return *(unsigned*)&p;
}

// ---- scratch ----
__device__ float g_xenc[BB * DX];
__device__ float g_h0[BB * DH];
__device__ float g_gates[(size_t)BB * TT * G3];   // 402 MB
__device__ float g_Ga[100 * G3];                  // a-vocab table
__device__ float g_Gt[4 * G3];                    // t-vocab table
__device__ float g_Gx[BB * G3];                   // per-batch (x_enc term + bih)

// ============================================================================
// K1: x_enc = x @ Wx^T + bx ; h0 = tanh([x_enc, eps0] @ W0^T + b0)
// ============================================================================
__global__ void k_enc(const float* __restrict__ x,  const float* __restrict__ Wx,
                      const float* __restrict__ bx, const float* __restrict__ eps,
                      const float* __restrict__ W0, const float* __restrict__ b0) {
    __shared__ float xs[64], xe[64], e0[16];
    int b = blockIdx.x, tid = threadIdx.x;
    if (tid < 64)                 xs[tid]      = x[b * 64 + tid];
    if (tid >= 64 && tid < 80)    e0[tid - 64] = eps[(size_t)b * TT * DEPS + (tid - 64)];
    __syncthreads();
    if (tid < 64) {
        float acc = bx[tid];
        #pragma unroll
        for (int k = 0; k < 64; k++) acc = fmaf(Wx[tid * 64 + k], xs[k], acc);
        xe[tid] = acc;
        g_xenc[b * 64 + tid] = acc;
    }
    __syncthreads();
    float acc = b0[tid];
    #pragma unroll
    for (int k = 0; k < 64; k++) acc = fmaf(W0[tid * 80 + k], xe[k], acc);
    #pragma unroll
    for (int k = 0; k < 16; k++) acc = fmaf(W0[tid * 80 + 64 + k], e0[k], acc);
    g_h0[b * DH + tid] = tanhf(acc);
}

// ============================================================================
// Table builders (exact fp32)
// ============================================================================
__global__ void k_tabA(const float* __restrict__ Ea, const float* __restrict__ Wih) {
    __shared__ float se[32];
    int v = blockIdx.x, g = threadIdx.x;
    if (g < 32) se[g] = Ea[v * 32 + g];
    __syncthreads();
    float acc = 0.f;
    #pragma unroll
    for (int k = 0; k < 32; k++) acc = fmaf(Wih[g * 129 + k], se[k], acc);
    g_Ga[v * G3 + g] = acc;
}

__global__ void k_tabT(const float* __restrict__ Et, const float* __restrict__ Wih) {
    __shared__ float se[16];
    int v = blockIdx.x, g = threadIdx.x;
    if (g < 16) se[g] = Et[v * 16 + g];
    __syncthreads();
    float acc = 0.f;
    #pragma unroll
    for (int k = 0; k < 16; k++) acc = fmaf(Wih[g * 129 + 32 + k], se[k], acc);
    g_Gt[v * G3 + g] = acc;
}

__global__ void k_tabX(const float* __restrict__ bih, const float* __restrict__ Wih) {
    __shared__ float sx[64];
    int b = blockIdx.x, g = threadIdx.x;
    if (g < 64) sx[g] = g_xenc[b * 64 + g];
    __syncthreads();
    float acc = bih[g];
    #pragma unroll
    for (int k = 0; k < 64; k++) acc = fmaf(Wih[g * 129 + 48 + k], sx[k], acc);
    g_Gx[b * G3 + g] = acc;
}

// ============================================================================
// K2: gates_x assembly: table gathers + exact fp32 eps term + prev_y term
// grid (TT/CH, BB), 384 threads (thread = gate)
// ============================================================================
__global__ void __launch_bounds__(384, 4)
k_gx(const int* __restrict__ a, const int* __restrict__ t,
     const float* __restrict__ y, const float* __restrict__ eps,
     const float* __restrict__ Wih) {
    __shared__ float seps[CH * 16];
    __shared__ float sGt[4 * G3];
    __shared__ int   sa[CH], st[CH];
    __shared__ float sy[CH];
    int tid = threadIdx.x;
    int b   = blockIdx.y;
    int s0  = blockIdx.x * CH;

    for (int i = tid; i < CH * 16; i += 384)
        seps[i] = eps[((size_t)b * TT + s0) * 16 + i];
    for (int i = tid; i < 4 * G3; i += 384)
        sGt[i] = g_Gt[i];
    if (tid < CH) {
        sa[tid] = a[b * TT + s0 + tid];
        st[tid] = t[b * TT + s0 + tid];
        int sp = s0 + tid;
        sy[tid] = (sp == 0) ? 0.f : y[b * TT + sp - 1];
    }
    float gxr = g_Gx[b * G3 + tid];
    float wyg = Wih[tid * 129 + 128];
    float we[16];
    #pragma unroll
    for (int k = 0; k < 16; k++) we[k] = Wih[tid * 129 + 112 + k];
    __syncthreads();

    #pragma unroll 4
    for (int p = 0; p < CH; p++) {
        float acc = fmaf(sy[p], wyg, gxr);
        acc += g_Ga[sa[p] * G3 + tid] + sGt[st[p] * G3 + tid];
        #pragma unroll
        for (int k = 0; k < 16; k++)
            acc = fmaf(we[k], seps[p * 16 + k], acc);
        g_gates[(((size_t)b * TT) + s0 + p) * G3 + tid] = acc;
    }
}

// ============================================================================
// K3: GRU scan via tensor cores (unchanged from R6)
// ============================================================================
__global__ void __launch_bounds__(384, 1)
k_rnn(const float* __restrict__ Whh, const float* __restrict__ bhh,
      const float* __restrict__ Wy,  const float* __restrict__ by,
      float* __restrict__ out) {
    __shared__ __align__(16) float hs[1024];
    __shared__ float Gh[8 * GH_S];
    __shared__ float As[1024], Bs[1024], Cs[1024], Ds[1024];
    __shared__ float Wys[128];
    __shared__ __nv_bfloat16 hhi[8 * HB_S], hlo[8 * HB_S];

    int tid = threadIdx.x;
    int b0r = blockIdx.x * 8;
    int warp = tid >> 5, lane = tid & 31;
    int grp = lane >> 2, q = lane & 3;

    unsigned Ahi[2][8][4], Alo[2][8][4];
    #pragma unroll
    for (int mt = 0; mt < 2; mt++)
        #pragma unroll
        for (int kc = 0; kc < 8; kc++)
            #pragma unroll
            for (int i = 0; i < 4; i++) {
                int g = warp * 32 + mt * 16 + grp + ((i & 1) ? 8 : 0);
                int k = kc * 16 + 2 * q + ((i & 2) ? 8 : 0);
                float2 wv = *(const float2*)&Whh[g * 128 + k];
                Ahi[mt][kc][i] = bfsplit_hi(wv.x, wv.y);
                Alo[mt][kc][i] = bfsplit_lo(wv.x, wv.y);
            }

    for (int i = tid; i < 1024; i += 384) {
        float h = g_h0[b0r * DH + i];
        hs[i] = h;
        int r = i >> 7, k = i & 127;
        __nv_bfloat16 hi = __float2bfloat16(h);
        hhi[r * HB_S + k] = hi;
        hlo[r * HB_S + k] = __float2bfloat16(h - __bfloat162float(hi));
    }
    if (tid < 128) Wys[tid] = Wy[tid];
    float bhh_j = bhh[tid];
    float by0   = by[0];
    __syncthreads();

    int sec = tid >> 7, jj = tid & 127;

    for (int t = 0; t < TT; t++) {
        float gx[8];
        #pragma unroll
        for (int r = 0; r < 8; r++)
            gx[r] = g_gates[((size_t)(b0r + r) * TT + t) * G3 + tid];

        float c0[4] = {0.f, 0.f, 0.f, 0.f}, c1[4] = {0.f, 0.f, 0.f, 0.f};
        #pragma unroll
        for (int kc = 0; kc < 8; kc++) {
            int koff = kc * 16 + 2 * q;
            unsigned bhi[2], blo[2];
            bhi[0] = *(const unsigned*)&hhi[grp * HB_S + koff];
            bhi[1] = *(const unsigned*)&hhi[grp * HB_S + koff + 8];
            blo[0] = *(const unsigned*)&hlo[grp * HB_S + koff];
            blo[1] = *(const unsigned*)&hlo[grp * HB_S + koff + 8];
            mma16816(c0, Ahi[0][kc], bhi);
            mma16816(c0, Alo[0][kc], bhi);
            mma16816(c0, Ahi[0][kc], blo);
            mma16816(c1, Ahi[1][kc], bhi);
            mma16816(c1, Alo[1][kc], bhi);
            mma16816(c1, Ahi[1][kc], blo);
        }
        {
            int gsc = warp * 32 + grp;
            Gh[(2 * q)     * GH_S + gsc]      = c0[0];
            Gh[(2 * q + 1) * GH_S + gsc]      = c0[1];
            Gh[(2 * q)     * GH_S + gsc + 8]  = c0[2];
            Gh[(2 * q + 1) * GH_S + gsc + 8]  = c0[3];
            Gh[(2 * q)     * GH_S + gsc + 16] = c1[0];
            Gh[(2 * q + 1) * GH_S + gsc + 16] = c1[1];
            Gh[(2 * q)     * GH_S + gsc + 24] = c1[2];
            Gh[(2 * q + 1) * GH_S + gsc + 24] = c1[3];
        }
        __syncthreads();

        #pragma unroll
        for (int r = 0; r < 8; r++) {
            float gh = Gh[r * GH_S + tid] + bhh_j;
            if (sec == 0) {
                As[r * 128 + jj] = 1.f / (1.f + expf(-(gx[r] + gh)));
            } else if (sec == 1) {
                Bs[r * 128 + jj] = 1.f / (1.f + expf(-(gx[r] + gh)));
            } else {
                Cs[r * 128 + jj] = gh;
                Ds[r * 128 + jj] = gx[r];
            }
        }
        __syncthreads();

        for (int i = tid; i < 1024; i += 384) {
            float rv = As[i], zv = Bs[i];
            float n  = tanhf(Ds[i] + rv * Cs[i]);
            float hn = (1.f - zv) * n + zv * hs[i];
            hs[i] = hn;
            int r = i >> 7, k = i & 127;
            __nv_bfloat16 hi = __float2bfloat16(hn);
            hhi[r * HB_S + k] = hi;
            hlo[r * HB_S + k] = __float2bfloat16(hn - __bfloat162float(hi));
        }
        __syncthreads();

        if (warp < 8) {
            float s = 0.f;
            #pragma unroll
            for (int m = 0; m < 4; m++)
                s = fmaf(hs[warp * 128 + lane + m * 32], Wys[lane + m * 32], s);
            s += __shfl_down_sync(0xffffffffu, s, 16);
            s += __shfl_down_sync(0xffffffffu, s, 8);
            s += __shfl_down_sync(0xffffffffu, s, 4);
            s += __shfl_down_sync(0xffffffffu, s, 2);
            s += __shfl_down_sync(0xffffffffu, s, 1);
            if (lane == 0) {
                float logit = s + by0;
                size_t o = ((size_t)(b0r + warp) * TT + t) * 2;
                out[o]     = logit;
                out[o + 1] = 1.f / (1.f + expf(-logit));
            }
        }
    }
}

// ============================================================================
extern "C" void kernel_launch(void* const* d_in, const int* in_sizes, int n_in,
                              void* d_out, int out_size) {
    const float* x   = (const float*)d_in[0];
    const int*   a   = (const int*)  d_in[1];
    const int*   t   = (const int*)  d_in[2];
    const float* y   = (const float*)d_in[3];
    const float* eps = (const float*)d_in[5];
    const float* Wx  = (const float*)d_in[6];
    const float* bx  = (const float*)d_in[7];
    const float* Ea  = (const float*)d_in[8];
    const float* Et  = (const float*)d_in[9];
    const float* Wih = (const float*)d_in[10];
    const float* Whh = (const float*)d_in[11];
    const float* bih = (const float*)d_in[12];
    const float* bhh = (const float*)d_in[13];
    const float* W0  = (const float*)d_in[14];
    const float* b0  = (const float*)d_in[15];
    const float* Wy  = (const float*)d_in[16];
    const float* by  = (const float*)d_in[17];
    float* out = (float*)d_out;

    k_enc<<<BB, 128>>>(x, Wx, bx, eps, W0, b0);
    k_tabA<<<100, G3>>>(Ea, Wih);
    k_tabT<<<4,   G3>>>(Et, Wih);
    k_tabX<<<BB,  G3>>>(bih, Wih);

    dim3 gg(TT / CH, BB);
    k_gx<<<gg, G3>>>(a, t, y, eps, Wih);

    k_rnn<<<BB / 8, 384>>>(Whh, bhh, Wy, by, out);
}

// round 8
// speedup vs baseline: 4.0468x; 1.0819x over previous
#include <cuda_runtime.h>
#include <cuda_bf16.h>
#include <math.h>

#define BB   1024
#define TT   256
#define DH   128
#define G3   384
#define DX   64
#define DEPS 16
#define GH_S 388    // Gh row stride (fp32) -> conflict-free MMA scatter
#define HB_S 136    // h bf16 row stride -> conflict-free b-frag loads
#define CH   64     // positions per k_gx block

// mma.sync m16n8k16 bf16 -> fp32
__device__ __forceinline__ void mma16816(float* c, const unsigned* a, const unsigned* b) {
    asm volatile(
        "mma.sync.aligned.m16n8k16.row.col.f32.bf16.bf16.f32 "
        "{%0,%1,%2,%3}, {%4,%5,%6,%7}, {%8,%9}, {%0,%1,%2,%3};"
        : "+f"(c[0]), "+f"(c[1]), "+f"(c[2]), "+f"(c[3])
        : "r"(a[0]), "r"(a[1]), "r"(a[2]), "r"(a[3]), "r"(b[0]), "r"(b[1]));
}
__device__ __forceinline__ unsigned bfsplit_hi(float x, float y) {
    __nv_bfloat162 p; p.x = __float2bfloat16(x); p.y = __float2bfloat16(y);
    return *(unsigned*)&p;
}
__device__ __forceinline__ unsigned bfsplit_lo(float x, float y) {
    __nv_bfloat162 p;
    p.x = __float2bfloat16(x - __bfloat162float(__float2bfloat16(x)));
    p.y = __float2bfloat16(y - __bfloat162float(__float2bfloat16(y)));
    return *(unsigned*)&p;
}
// fast sigmoid/tanh via ex2.approx + rcp.approx (rel err ~1e-6)
__device__ __forceinline__ float fsigmoid(float x) {
    float e, r;
    asm("ex2.approx.f32 %0, %1;" : "=f"(e) : "f"(-1.4426950408889634f * x));
    asm("rcp.approx.f32 %0, %1;" : "=f"(r) : "f"(1.f + e));
    return r;
}
__device__ __forceinline__ float ftanh(float x) {
    float e, r;
    asm("ex2.approx.f32 %0, %1;" : "=f"(e) : "f"(-2.8853900817779268f * x));
    asm("rcp.approx.f32 %0, %1;" : "=f"(r) : "f"(1.f + e));
    return fmaf(2.f, r, -1.f);
}

// ---- scratch ----
__device__ float g_xenc[BB * DX];
__device__ float g_h0[BB * DH];
__device__ float g_gates[(size_t)BB * TT * G3];   // 402 MB
__device__ float g_Ga[100 * G3];
__device__ float g_Gt[4 * G3];
__device__ float g_Gx[BB * G3];

// ============================================================================
// K1: x_enc + h0
// ============================================================================
__global__ void k_enc(const float* __restrict__ x,  const float* __restrict__ Wx,
                      const float* __restrict__ bx, const float* __restrict__ eps,
                      const float* __restrict__ W0, const float* __restrict__ b0) {
    __shared__ float xs[64], xe[64], e0[16];
    int b = blockIdx.x, tid = threadIdx.x;
    if (tid < 64)                 xs[tid]      = x[b * 64 + tid];
    if (tid >= 64 && tid < 80)    e0[tid - 64] = eps[(size_t)b * TT * DEPS + (tid - 64)];
    __syncthreads();
    if (tid < 64) {
        float acc = bx[tid];
        #pragma unroll
        for (int k = 0; k < 64; k++) acc = fmaf(Wx[tid * 64 + k], xs[k], acc);
        xe[tid] = acc;
        g_xenc[b * 64 + tid] = acc;
    }
    __syncthreads();
    float acc = b0[tid];
    #pragma unroll
    for (int k = 0; k < 64; k++) acc = fmaf(W0[tid * 80 + k], xe[k], acc);
    #pragma unroll
    for (int k = 0; k < 16; k++) acc = fmaf(W0[tid * 80 + 64 + k], e0[k], acc);
    g_h0[b * DH + tid] = tanhf(acc);
}

// ============================================================================
// Table builders (exact fp32)
// ============================================================================
__global__ void k_tabA(const float* __restrict__ Ea, const float* __restrict__ Wih) {
    __shared__ float se[32];
    int v = blockIdx.x, g = threadIdx.x;
    if (g < 32) se[g] = Ea[v * 32 + g];
    __syncthreads();
    float acc = 0.f;
    #pragma unroll
    for (int k = 0; k < 32; k++) acc = fmaf(Wih[g * 129 + k], se[k], acc);
    g_Ga[v * G3 + g] = acc;
}

__global__ void k_tabT(const float* __restrict__ Et, const float* __restrict__ Wih) {
    __shared__ float se[16];
    int v = blockIdx.x, g = threadIdx.x;
    if (g < 16) se[g] = Et[v * 16 + g];
    __syncthreads();
    float acc = 0.f;
    #pragma unroll
    for (int k = 0; k < 16; k++) acc = fmaf(Wih[g * 129 + 32 + k], se[k], acc);
    g_Gt[v * G3 + g] = acc;
}

__global__ void k_tabX(const float* __restrict__ bih, const float* __restrict__ Wih) {
    __shared__ float sx[64];
    int b = blockIdx.x, g = threadIdx.x;
    if (g < 64) sx[g] = g_xenc[b * 64 + g];
    __syncthreads();
    float acc = bih[g];
    #pragma unroll
    for (int k = 0; k < 64; k++) acc = fmaf(Wih[g * 129 + 48 + k], sx[k], acc);
    g_Gx[b * G3 + g] = acc;
}

// ============================================================================
// K2: gates_x assembly (unchanged from R7)
// ============================================================================
__global__ void __launch_bounds__(384, 4)
k_gx(const int* __restrict__ a, const int* __restrict__ t,
     const float* __restrict__ y, const float* __restrict__ eps,
     const float* __restrict__ Wih) {
    __shared__ float seps[CH * 16];
    __shared__ float sGt[4 * G3];
    __shared__ int   sa[CH], st[CH];
    __shared__ float sy[CH];
    int tid = threadIdx.x;
    int b   = blockIdx.y;
    int s0  = blockIdx.x * CH;

    for (int i = tid; i < CH * 16; i += 384)
        seps[i] = eps[((size_t)b * TT + s0) * 16 + i];
    for (int i = tid; i < 4 * G3; i += 384)
        sGt[i] = g_Gt[i];
    if (tid < CH) {
        sa[tid] = a[b * TT + s0 + tid];
        st[tid] = t[b * TT + s0 + tid];
        int sp = s0 + tid;
        sy[tid] = (sp == 0) ? 0.f : y[b * TT + sp - 1];
    }
    float gxr = g_Gx[b * G3 + tid];
    float wyg = Wih[tid * 129 + 128];
    float we[16];
    #pragma unroll
    for (int k = 0; k < 16; k++) we[k] = Wih[tid * 129 + 112 + k];
    __syncthreads();

    #pragma unroll 4
    for (int p = 0; p < CH; p++) {
        float acc = fmaf(sy[p], wyg, gxr);
        acc += g_Ga[sa[p] * G3 + tid] + sGt[st[p] * G3 + tid];
        #pragma unroll
        for (int k = 0; k < 16; k++)
            acc = fmaf(we[k], seps[p * 16 + k], acc);
        g_gates[(((size_t)b * TT) + s0 + p) * G3 + tid] = acc;
    }
}

// ============================================================================
// K3: GRU scan, restructured:
//  - 2 barriers/step (gate exchange arrays eliminated; fused gate+h update)
//  - 4 independent MMA accumulator chains (even/odd kc)
//  - approx sigmoid/tanh (ex2+rcp)
// ============================================================================
__global__ void __launch_bounds__(384, 1)
k_rnn(const float* __restrict__ Whh, const float* __restrict__ bhh,
      const float* __restrict__ Wy,  const float* __restrict__ by,
      float* __restrict__ out) {
    __shared__ __align__(16) float hs[1024];
    __shared__ float Gh[8 * GH_S];
    __shared__ float Wys[128];
    __shared__ float sbhh[G3];
    __shared__ __nv_bfloat16 hhi[8 * HB_S], hlo[8 * HB_S];

    int tid = threadIdx.x;
    int b0r = blockIdx.x * 8;
    int warp = tid >> 5, lane = tid & 31;
    int grp = lane >> 2, q = lane & 3;

    // Whh A-fragments (split bf16) resident in registers for all 256 steps
    unsigned Ahi[2][8][4], Alo[2][8][4];
    #pragma unroll
    for (int mt = 0; mt < 2; mt++)
        #pragma unroll
        for (int kc = 0; kc < 8; kc++)
            #pragma unroll
            for (int i = 0; i < 4; i++) {
                int g = warp * 32 + mt * 16 + grp + ((i & 1) ? 8 : 0);
                int k = kc * 16 + 2 * q + ((i & 2) ? 8 : 0);
                float2 wv = *(const float2*)&Whh[g * 128 + k];
                Ahi[mt][kc][i] = bfsplit_hi(wv.x, wv.y);
                Alo[mt][kc][i] = bfsplit_lo(wv.x, wv.y);
            }

    for (int i = tid; i < 1024; i += 384) {
        float h = g_h0[b0r * DH + i];
        hs[i] = h;
        int r = i >> 7, k = i & 127;
        __nv_bfloat16 hi = __float2bfloat16(h);
        hhi[r * HB_S + k] = hi;
        hlo[r * HB_S + k] = __float2bfloat16(h - __bfloat162float(hi));
    }
    if (tid < 128) Wys[tid] = Wy[tid];
    sbhh[tid] = bhh[tid];
    float by0 = by[0];
    __syncthreads();

    for (int t = 0; t < TT; t++) {
        // prefetch gx (overlaps MMA chain)
        float gxv[3][3];
        #pragma unroll
        for (int it = 0; it < 3; it++) {
            int i = tid + it * 384;
            if (it < 2 || tid < 256) {
                int r = i >> 7, j = i & 127;
                const float* gp = &g_gates[((size_t)(b0r + r) * TT + t) * G3 + j];
                gxv[it][0] = gp[0];
                gxv[it][1] = gp[128];
                gxv[it][2] = gp[256];
            }
        }

        // MMA: gh = Whh @ h^T, 4 independent accumulator chains
        float c0a[4] = {0,0,0,0}, c0b[4] = {0,0,0,0};
        float c1a[4] = {0,0,0,0}, c1b[4] = {0,0,0,0};
        #pragma unroll
        for (int kc = 0; kc < 8; kc++) {
            int koff = kc * 16 + 2 * q;
            unsigned bhi[2], blo[2];
            bhi[0] = *(const unsigned*)&hhi[grp * HB_S + koff];
            bhi[1] = *(const unsigned*)&hhi[grp * HB_S + koff + 8];
            blo[0] = *(const unsigned*)&hlo[grp * HB_S + koff];
            blo[1] = *(const unsigned*)&hlo[grp * HB_S + koff + 8];
            float* d0 = (kc & 1) ? c0b : c0a;
            float* d1 = (kc & 1) ? c1b : c1a;
            mma16816(d0, Ahi[0][kc], bhi);
            mma16816(d1, Ahi[1][kc], bhi);
            mma16816(d0, Alo[0][kc], bhi);
            mma16816(d1, Alo[1][kc], bhi);
            mma16816(d0, Ahi[0][kc], blo);
            mma16816(d1, Ahi[1][kc], blo);
        }
        {
            int gsc = warp * 32 + grp;
            Gh[(2*q)   * GH_S + gsc]      = c0a[0] + c0b[0];
            Gh[(2*q+1) * GH_S + gsc]      = c0a[1] + c0b[1];
            Gh[(2*q)   * GH_S + gsc + 8]  = c0a[2] + c0b[2];
            Gh[(2*q+1) * GH_S + gsc + 8]  = c0a[3] + c0b[3];
            Gh[(2*q)   * GH_S + gsc + 16] = c1a[0] + c1b[0];
            Gh[(2*q+1) * GH_S + gsc + 16] = c1a[1] + c1b[1];
            Gh[(2*q)   * GH_S + gsc + 24] = c1a[2] + c1b[2];
            Gh[(2*q+1) * GH_S + gsc + 24] = c1a[3] + c1b[3];
        }
        __syncthreads();

        // fused gates + h update (thread owns unit-rows i, i+384, i+768)
        #pragma unroll
        for (int it = 0; it < 3; it++) {
            int i = tid + it * 384;
            if (it == 2 && tid >= 256) break;
            int r = i >> 7, j = i & 127;
            float ghr = Gh[r * GH_S + j]       + sbhh[j];
            float ghz = Gh[r * GH_S + j + 128] + sbhh[j + 128];
            float ghn = Gh[r * GH_S + j + 256] + sbhh[j + 256];
            float rv = fsigmoid(gxv[it][0] + ghr);
            float zv = fsigmoid(gxv[it][1] + ghz);
            float nv = ftanh(gxv[it][2] + rv * ghn);
            float hn = (1.f - zv) * nv + zv * hs[i];
            hs[i] = hn;
            __nv_bfloat16 hi = __float2bfloat16(hn);
            hhi[r * HB_S + j] = hi;
            hlo[r * HB_S + j] = __float2bfloat16(hn - __bfloat162float(hi));
        }
        __syncthreads();

        // logits + sigmoid, one warp per row (runs while warps 8-11 start next MMA)
        if (warp < 8) {
            float s = 0.f;
            #pragma unroll
            for (int m = 0; m < 4; m++)
                s = fmaf(hs[warp * 128 + lane + m * 32], Wys[lane + m * 32], s);
            s += __shfl_down_sync(0xffffffffu, s, 16);
            s += __shfl_down_sync(0xffffffffu, s, 8);
            s += __shfl_down_sync(0xffffffffu, s, 4);
            s += __shfl_down_sync(0xffffffffu, s, 2);
            s += __shfl_down_sync(0xffffffffu, s, 1);
            if (lane == 0) {
                float logit = s + by0;
                size_t o = ((size_t)(b0r + warp) * TT + t) * 2;
                out[o]     = logit;
                out[o + 1] = fsigmoid(logit);
            }
        }
    }
}

// ============================================================================
extern "C" void kernel_launch(void* const* d_in, const int* in_sizes, int n_in,
                              void* d_out, int out_size) {
    const float* x   = (const float*)d_in[0];
    const int*   a   = (const int*)  d_in[1];
    const int*   t   = (const int*)  d_in[2];
    const float* y   = (const float*)d_in[3];
    const float* eps = (const float*)d_in[5];
    const float* Wx  = (const float*)d_in[6];
    const float* bx  = (const float*)d_in[7];
    const float* Ea  = (const float*)d_in[8];
    const float* Et  = (const float*)d_in[9];
    const float* Wih = (const float*)d_in[10];
    const float* Whh = (const float*)d_in[11];
    const float* bih = (const float*)d_in[12];
    const float* bhh = (const float*)d_in[13];
    const float* W0  = (const float*)d_in[14];
    const float* b0  = (const float*)d_in[15];
    const float* Wy  = (const float*)d_in[16];
    const float* by  = (const float*)d_in[17];
    float* out = (float*)d_out;

    k_enc<<<BB, 128>>>(x, Wx, bx, eps, W0, b0);
    k_tabA<<<100, G3>>>(Ea, Wih);
    k_tabT<<<4,   G3>>>(Et, Wih);
    k_tabX<<<BB,  G3>>>(bih, Wih);

    dim3 gg(TT / CH, BB);
    k_gx<<<gg, G3>>>(a, t, y, eps, Wih);

    k_rnn<<<BB / 8, 384>>>(Whh, bhh, Wy, by, out);
}

// round 9
// speedup vs baseline: 4.3769x; 1.0816x over previous
#include <cuda_runtime.h>
#include <cuda_bf16.h>
#include <math.h>

#define BB   1024
#define TT   256
#define DH   128
#define G3   384
#define DX   64
#define DEPS 16
#define GH_S 388    // Gh/sEps row stride (fp32) -> conflict-free MMA scatter
#define HB_S 136    // h bf16 row stride -> conflict-free b-frag loads

// mma.sync m16n8k16 bf16 -> fp32
__device__ __forceinline__ void mma16816(float* c, const unsigned* a, const unsigned* b) {
    asm volatile(
        "mma.sync.aligned.m16n8k16.row.col.f32.bf16.bf16.f32 "
        "{%0,%1,%2,%3}, {%4,%5,%6,%7}, {%8,%9}, {%0,%1,%2,%3};"
        : "+f"(c[0]), "+f"(c[1]), "+f"(c[2]), "+f"(c[3])
        : "r"(a[0]), "r"(a[1]), "r"(a[2]), "r"(a[3]), "r"(b[0]), "r"(b[1]));
}
__device__ __forceinline__ unsigned bfsplit_hi(float x, float y) {
    __nv_bfloat162 p; p.x = __float2bfloat16(x); p.y = __float2bfloat16(y);
    return *(unsigned*)&p;
}
__device__ __forceinline__ unsigned bfsplit_lo(float x, float y) {
    __nv_bfloat162 p;
    p.x = __float2bfloat16(x - __bfloat162float(__float2bfloat16(x)));
    p.y = __float2bfloat16(y - __bfloat162float(__float2bfloat16(y)));
    return *(unsigned*)&p;
}
__device__ __forceinline__ float fsigmoid(float x) {
    float e, r;
    asm("ex2.approx.f32 %0, %1;" : "=f"(e) : "f"(-1.4426950408889634f * x));
    asm("rcp.approx.f32 %0, %1;" : "=f"(r) : "f"(1.f + e));
    return r;
}
__device__ __forceinline__ float ftanh(float x) {
    float e, r;
    asm("ex2.approx.f32 %0, %1;" : "=f"(e) : "f"(-2.8853900817779268f * x));
    asm("rcp.approx.f32 %0, %1;" : "=f"(r) : "f"(1.f + e));
    return fmaf(2.f, r, -1.f);
}
__device__ __forceinline__ void cp4(unsigned dst, const void* src) {
    asm volatile("cp.async.ca.shared.global [%0], [%1], 4;" :: "r"(dst), "l"(src));
}

// ---- scratch ----
__device__ float g_xenc[BB * DX];
__device__ float g_h0[BB * DH];
__device__ float g_Ga[100 * G3];
__device__ float g_Gt[4 * G3];
__device__ float g_Gx[BB * G3];

// ============================================================================
// K1: x_enc + h0
// ============================================================================
__global__ void k_enc(const float* __restrict__ x,  const float* __restrict__ Wx,
                      const float* __restrict__ bx, const float* __restrict__ eps,
                      const float* __restrict__ W0, const float* __restrict__ b0) {
    __shared__ float xs[64], xe[64], e0[16];
    int b = blockIdx.x, tid = threadIdx.x;
    if (tid < 64)                 xs[tid]      = x[b * 64 + tid];
    if (tid >= 64 && tid < 80)    e0[tid - 64] = eps[(size_t)b * TT * DEPS + (tid - 64)];
    __syncthreads();
    if (tid < 64) {
        float acc = bx[tid];
        #pragma unroll
        for (int k = 0; k < 64; k++) acc = fmaf(Wx[tid * 64 + k], xs[k], acc);
        xe[tid] = acc;
        g_xenc[b * 64 + tid] = acc;
    }
    __syncthreads();
    float acc = b0[tid];
    #pragma unroll
    for (int k = 0; k < 64; k++) acc = fmaf(W0[tid * 80 + k], xe[k], acc);
    #pragma unroll
    for (int k = 0; k < 16; k++) acc = fmaf(W0[tid * 80 + 64 + k], e0[k], acc);
    g_h0[b * DH + tid] = tanhf(acc);
}

// ============================================================================
// Table builders (exact fp32)
// ============================================================================
__global__ void k_tabA(const float* __restrict__ Ea, const float* __restrict__ Wih) {
    __shared__ float se[32];
    int v = blockIdx.x, g = threadIdx.x;
    if (g < 32) se[g] = Ea[v * 32 + g];
    __syncthreads();
    float acc = 0.f;
    #pragma unroll
    for (int k = 0; k < 32; k++) acc = fmaf(Wih[g * 129 + k], se[k], acc);
    g_Ga[v * G3 + g] = acc;
}
__global__ void k_tabT(const float* __restrict__ Et, const float* __restrict__ Wih) {
    __shared__ float se[16];
    int v = blockIdx.x, g = threadIdx.x;
    if (g < 16) se[g] = Et[v * 16 + g];
    __syncthreads();
    float acc = 0.f;
    #pragma unroll
    for (int k = 0; k < 16; k++) acc = fmaf(Wih[g * 129 + 32 + k], se[k], acc);
    g_Gt[v * G3 + g] = acc;
}
__global__ void k_tabX(const float* __restrict__ bih, const float* __restrict__ Wih) {
    __shared__ float sx[64];
    int b = blockIdx.x, g = threadIdx.x;
    if (g < 64) sx[g] = g_xenc[b * 64 + g];
    __syncthreads();
    float acc = bih[g];
    #pragma unroll
    for (int k = 0; k < 64; k++) acc = fmaf(Wih[g * 129 + 48 + k], sx[k], acc);
    g_Gx[b * G3 + g] = acc;
}

// ============================================================================
// K3: fully fused GRU scan. No g_gates: input-gate terms assembled in-kernel
// (Ga/Gt/Gx tables + y term in SMEM; eps term as a K=16 split-bf16 MMA).
// ============================================================================
// dynamic smem layout (floats unless noted):
// hs 1024 | Gh 3104 | sEps 3104 | sbhh 384 | Wys 128 | sGxb 3072 | sGt 1536 |
// swyg 384 | sGxs 3072 | sga 6144 | sWeAhi 3456u | sWeAlo 3456u |
// hhi 1088bf | hlo 1088bf | epshi 320bf | epslo 320bf | scode 2048s
#define SMB (21952 * 4 + 6912 * 4 + 2816 * 2 + 2048 * 2)

__global__ void __launch_bounds__(384, 1)
k_rnn(const int* __restrict__ a, const int* __restrict__ tcat,
      const float* __restrict__ y, const float* __restrict__ eps,
      const float* __restrict__ Wih,
      const float* __restrict__ Whh, const float* __restrict__ bhh,
      const float* __restrict__ Wy,  const float* __restrict__ by,
      float* __restrict__ out) {
    extern __shared__ __align__(16) char smraw[];
    float* hs    = (float*)smraw;
    float* Gh    = hs + 1024;
    float* sEps  = Gh + 3104;
    float* sbhh  = sEps + 3104;
    float* Wys   = sbhh + 384;
    float* sGxb  = Wys + 128;
    float* sGt   = sGxb + 3072;
    float* swyg  = sGt + 1536;
    float* sGxs  = swyg + 384;
    float* sga   = sGxs + 3072;
    unsigned* sWeAhi = (unsigned*)(sga + 6144);
    unsigned* sWeAlo = sWeAhi + 3456;
    __nv_bfloat16* hhi   = (__nv_bfloat16*)(sWeAlo + 3456);
    __nv_bfloat16* hlo   = hhi + 1088;
    __nv_bfloat16* epshi = hlo + 1088;
    __nv_bfloat16* epslo = epshi + 320;
    short* scode = (short*)(epslo + 320);

    int tid = threadIdx.x;
    int b0r = blockIdx.x * 8;
    int warp = tid >> 5, lane = tid & 31;
    int grp = lane >> 2, q = lane & 3;

    // ---- Whh A-fragments (split bf16) resident in registers ----
    unsigned Ahi[2][8][4], Alo[2][8][4];
    #pragma unroll
    for (int mt = 0; mt < 2; mt++)
        #pragma unroll
        for (int kc = 0; kc < 8; kc++)
            #pragma unroll
            for (int i = 0; i < 4; i++) {
                int g = warp * 32 + mt * 16 + grp + ((i & 1) ? 8 : 0);
                int k = kc * 16 + 2 * q + ((i & 2) ? 8 : 0);
                float2 wv = *(const float2*)&Whh[g * 128 + k];
                Ahi[mt][kc][i] = bfsplit_hi(wv.x, wv.y);
                Alo[mt][kc][i] = bfsplit_lo(wv.x, wv.y);
            }

    // ---- prologue: tables, codes, weights, h0 ----
    for (int i = tid; i < 2048; i += 384) {
        int r = i >> 8, s = i & 255;
        int av = a[(b0r + r) * TT + s];
        int tv = tcat[(b0r + r) * TT + s];
        int yb = (s == 0) ? 0 : (y[(b0r + r) * TT + s - 1] > 0.5f ? 1 : 0);
        scode[i] = (short)(av | (tv << 7) | (yb << 9));
    }
    for (int i = tid; i < 3072; i += 384) sGxb[i] = g_Gx[b0r * G3 + i];
    for (int i = tid; i < 1536; i += 384) sGt[i]  = g_Gt[i];
    {
        int g = tid;
        swyg[g] = Wih[g * 129 + 128];
        #pragma unroll
        for (int k2 = 0; k2 < 8; k2++) {
            float w0 = Wih[g * 129 + 112 + 2 * k2];
            float w1 = Wih[g * 129 + 112 + 2 * k2 + 1];
            sWeAhi[g * 9 + k2] = bfsplit_hi(w0, w1);
            sWeAlo[g * 9 + k2] = bfsplit_lo(w0, w1);
        }
    }
    for (int i = tid; i < 1024; i += 384) {
        float h = g_h0[b0r * DH + i];
        hs[i] = h;
        int r = i >> 7, k = i & 127;
        __nv_bfloat16 hi = __float2bfloat16(h);
        hhi[r * HB_S + k] = hi;
        hlo[r * HB_S + k] = __float2bfloat16(h - __bfloat162float(hi));
    }
    sbhh[tid] = bhh[tid];
    if (tid < 128) Wys[tid] = Wy[tid];
    float by0 = by[0];
    __syncthreads();   // scode visible

    // sga[0], eps[0]
    #pragma unroll
    for (int r = 0; r < 8; r++) {
        int ca = scode[r * 256] & 127;
        sga[r * 384 + tid] = g_Ga[ca * G3 + tid];
    }
    if (tid < 128) {
        int r = tid >> 4, k = tid & 15;
        float v = eps[((size_t)(b0r + r) * TT) * 16 + k];
        __nv_bfloat16 hi = __float2bfloat16(v);
        epshi[r * 20 + k] = hi;
        epslo[r * 20 + k] = __float2bfloat16(v - __bfloat162float(hi));
    }
    __syncthreads();

    unsigned sga_addr = (unsigned)__cvta_generic_to_shared(sga);

    for (int t = 0; t < TT; t++) {
        int buf = t & 1, nbuf = buf ^ 1;
        int tp1 = (t + 1) & 255;   // wrap: t=255 prefetch is dead but in-bounds

        // ---- prefetch t+1 ----
        float epv = 0.f;
        if (tid < 128)
            epv = eps[((size_t)(b0r + (tid >> 4)) * TT + tp1) * 16 + (tid & 15)];
        #pragma unroll
        for (int r = 0; r < 8; r++) {
            int ca = scode[r * 256 + tp1] & 127;
            cp4(sga_addr + (unsigned)(nbuf * 3072 + r * 384 + tid) * 4,
                &g_Ga[ca * G3 + tid]);
        }
        asm volatile("cp.async.commit_group;");

        // ---- eps-MMA (K=16, split bf16) -> sEps ----
        {
            unsigned bh[2], bl[2];
            bh[0] = *(unsigned*)&epshi[buf * 160 + grp * 20 + 2 * q];
            bh[1] = *(unsigned*)&epshi[buf * 160 + grp * 20 + 2 * q + 8];
            bl[0] = *(unsigned*)&epslo[buf * 160 + grp * 20 + 2 * q];
            bl[1] = *(unsigned*)&epslo[buf * 160 + grp * 20 + 2 * q + 8];
            float ce0[4] = {0,0,0,0}, ce1[4] = {0,0,0,0};
            #pragma unroll
            for (int mt = 0; mt < 2; mt++) {
                int gb = warp * 32 + mt * 16;
                unsigned ah[4], al[4];
                ah[0] = sWeAhi[(gb + grp) * 9 + q];
                ah[1] = sWeAhi[(gb + grp + 8) * 9 + q];
                ah[2] = sWeAhi[(gb + grp) * 9 + q + 4];
                ah[3] = sWeAhi[(gb + grp + 8) * 9 + q + 4];
                al[0] = sWeAlo[(gb + grp) * 9 + q];
                al[1] = sWeAlo[(gb + grp + 8) * 9 + q];
                al[2] = sWeAlo[(gb + grp) * 9 + q + 4];
                al[3] = sWeAlo[(gb + grp + 8) * 9 + q + 4];
                float* d = mt ? ce1 : ce0;
                mma16816(d, ah, bh);
                mma16816(d, ah, bl);
                mma16816(d, al, bh);
            }
            int gsc = warp * 32 + grp;
            sEps[(2*q)   * GH_S + gsc]      = ce0[0];
            sEps[(2*q+1) * GH_S + gsc]      = ce0[1];
            sEps[(2*q)   * GH_S + gsc + 8]  = ce0[2];
            sEps[(2*q+1) * GH_S + gsc + 8]  = ce0[3];
            sEps[(2*q)   * GH_S + gsc + 16] = ce1[0];
            sEps[(2*q+1) * GH_S + gsc + 16] = ce1[1];
            sEps[(2*q)   * GH_S + gsc + 24] = ce1[2];
            sEps[(2*q+1) * GH_S + gsc + 24] = ce1[3];
        }

        // ---- h-MMA: gh = Whh @ h^T ----
        float c0a[4] = {0,0,0,0}, c0b[4] = {0,0,0,0};
        float c1a[4] = {0,0,0,0}, c1b[4] = {0,0,0,0};
        #pragma unroll
        for (int kc = 0; kc < 8; kc++) {
            int koff = kc * 16 + 2 * q;
            unsigned bhh2[2], bll[2];
            bhh2[0] = *(const unsigned*)&hhi[grp * HB_S + koff];
            bhh2[1] = *(const unsigned*)&hhi[grp * HB_S + koff + 8];
            bll[0]  = *(const unsigned*)&hlo[grp * HB_S + koff];
            bll[1]  = *(const unsigned*)&hlo[grp * HB_S + koff + 8];
            float* d0 = (kc & 1) ? c0b : c0a;
            float* d1 = (kc & 1) ? c1b : c1a;
            mma16816(d0, Ahi[0][kc], bhh2);
            mma16816(d1, Ahi[1][kc], bhh2);
            mma16816(d0, Alo[0][kc], bhh2);
            mma16816(d1, Alo[1][kc], bhh2);
            mma16816(d0, Ahi[0][kc], bll);
            mma16816(d1, Ahi[1][kc], bll);
        }
        {
            int gsc = warp * 32 + grp;
            Gh[(2*q)   * GH_S + gsc]      = c0a[0] + c0b[0];
            Gh[(2*q+1) * GH_S + gsc]      = c0a[1] + c0b[1];
            Gh[(2*q)   * GH_S + gsc + 8]  = c0a[2] + c0b[2];
            Gh[(2*q+1) * GH_S + gsc + 8]  = c0a[3] + c0b[3];
            Gh[(2*q)   * GH_S + gsc + 16] = c1a[0] + c1b[0];
            Gh[(2*q+1) * GH_S + gsc + 16] = c1a[1] + c1b[1];
            Gh[(2*q)   * GH_S + gsc + 24] = c1a[2] + c1b[2];
            Gh[(2*q+1) * GH_S + gsc + 24] = c1a[3] + c1b[3];
        }

        // ---- gx assembly (thread = gate, 8 rows); own-slot cp.async data ----
        asm volatile("cp.async.wait_group 1;");
        #pragma unroll
        for (int r = 0; r < 8; r++) {
            int code = scode[r * 256 + t];
            float acc = sga[buf * 3072 + r * 384 + tid]
                      + sGt[((code >> 7) & 3) * G3 + tid]
                      + sGxb[r * 384 + tid];
            if (code & 512) acc += swyg[tid];
            sGxs[r * 384 + tid] = acc;
        }

        // ---- stage eps(t+1) split ----
        if (tid < 128) {
            int r = tid >> 4, k = tid & 15;
            __nv_bfloat16 hi = __float2bfloat16(epv);
            epshi[nbuf * 160 + r * 20 + k] = hi;
            epslo[nbuf * 160 + r * 20 + k] = __float2bfloat16(epv - __bfloat162float(hi));
        }
        __syncthreads();

        // ---- fused gates + h update ----
        #pragma unroll
        for (int it = 0; it < 3; it++) {
            int i = tid + it * 384;
            if (it == 2 && tid >= 256) break;
            int r = i >> 7, j = i & 127;
            float ghr = Gh[r * GH_S + j]       + sbhh[j];
            float ghz = Gh[r * GH_S + j + 128] + sbhh[j + 128];
            float ghn = Gh[r * GH_S + j + 256] + sbhh[j + 256];
            float gxr = sGxs[r * 384 + j]       + sEps[r * GH_S + j];
            float gxz = sGxs[r * 384 + j + 128] + sEps[r * GH_S + j + 128];
            float gxn = sGxs[r * 384 + j + 256] + sEps[r * GH_S + j + 256];
            float rv = fsigmoid(gxr + ghr);
            float zv = fsigmoid(gxz + ghz);
            float nv = ftanh(gxn + rv * ghn);
            float hn = (1.f - zv) * nv + zv * hs[i];
            hs[i] = hn;
            __nv_bfloat16 hi = __float2bfloat16(hn);
            hhi[r * HB_S + j] = hi;
            hlo[r * HB_S + j] = __float2bfloat16(hn - __bfloat162float(hi));
        }
        __syncthreads();

        // ---- output epilogue (overlaps next step's MMA for warps 8-11) ----
        if (warp < 8) {
            float s = 0.f;
            #pragma unroll
            for (int m = 0; m < 4; m++)
                s = fmaf(hs[warp * 128 + lane + m * 32], Wys[lane + m * 32], s);
            s += __shfl_down_sync(0xffffffffu, s, 16);
            s += __shfl_down_sync(0xffffffffu, s, 8);
            s += __shfl_down_sync(0xffffffffu, s, 4);
            s += __shfl_down_sync(0xffffffffu, s, 2);
            s += __shfl_down_sync(0xffffffffu, s, 1);
            if (lane == 0) {
                float logit = s + by0;
                size_t o = ((size_t)(b0r + warp) * TT + t) * 2;
                out[o]     = logit;
                out[o + 1] = fsigmoid(logit);
            }
        }
    }
    asm volatile("cp.async.wait_group 0;");
}

// ============================================================================
extern "C" void kernel_launch(void* const* d_in, const int* in_sizes, int n_in,
                              void* d_out, int out_size) {
    const float* x   = (const float*)d_in[0];
    const int*   a   = (const int*)  d_in[1];
    const int*   t   = (const int*)  d_in[2];
    const float* y   = (const float*)d_in[3];
    const float* eps = (const float*)d_in[5];
    const float* Wx  = (const float*)d_in[6];
    const float* bx  = (const float*)d_in[7];
    const float* Ea  = (const float*)d_in[8];
    const float* Et  = (const float*)d_in[9];
    const float* Wih = (const float*)d_in[10];
    const float* Whh = (const float*)d_in[11];
    const float* bih = (const float*)d_in[12];
    const float* bhh = (const float*)d_in[13];
    const float* W0  = (const float*)d_in[14];
    const float* b0  = (const float*)d_in[15];
    const float* Wy  = (const float*)d_in[16];
    const float* by  = (const float*)d_in[17];
    float* out = (float*)d_out;

    cudaFuncSetAttribute(k_rnn, cudaFuncAttributeMaxDynamicSharedMemorySize, SMB);

    k_enc<<<BB, 128>>>(x, Wx, bx, eps, W0, b0);
    k_tabA<<<100, G3>>>(Ea, Wih);
    k_tabT<<<4,   G3>>>(Et, Wih);
    k_tabX<<<BB,  G3>>>(bih, Wih);

    k_rnn<<<BB / 8, 384, SMB>>>(a, t, y, eps, Wih, Whh, bhh, Wy, by, out);
}

// round 11
// speedup vs baseline: 4.4947x; 1.0269x over previous
#include <cuda_runtime.h>
#include <cuda_bf16.h>
#include <math.h>

#define BB   1024
#define TT   256
#define DH   128
#define G3   384
#define DX   64
#define DEPS 16
#define NB   152    // k_rnn blocks (one per SM)
#define GH_S 388    // Gh/sEps row stride (fp32) -> conflict-free MMA scatter
#define HB_S 136    // h bf16 row stride -> conflict-free b-frag loads

// mma.sync m16n8k16 bf16 -> fp32
__device__ __forceinline__ void mma16816(float* c, const unsigned* a, const unsigned* b) {
    asm volatile(
        "mma.sync.aligned.m16n8k16.row.col.f32.bf16.bf16.f32 "
        "{%0,%1,%2,%3}, {%4,%5,%6,%7}, {%8,%9}, {%0,%1,%2,%3};"
        : "+f"(c[0]), "+f"(c[1]), "+f"(c[2]), "+f"(c[3])
        : "r"(a[0]), "r"(a[1]), "r"(a[2]), "r"(a[3]), "r"(b[0]), "r"(b[1]));
}
__device__ __forceinline__ unsigned bfsplit_hi(float x, float y) {
    __nv_bfloat162 p; p.x = __float2bfloat16(x); p.y = __float2bfloat16(y);
    return *(unsigned*)&p;
}
__device__ __forceinline__ unsigned bfsplit_lo(float x, float y) {
    __nv_bfloat162 p;
    p.x = __float2bfloat16(x - __bfloat162float(__float2bfloat16(x)));
    p.y = __float2bfloat16(y - __bfloat162float(__float2bfloat16(y)));
    return *(unsigned*)&p;
}
__device__ __forceinline__ float fsigmoid(float x) {
    float e, r;
    asm("ex2.approx.f32 %0, %1;" : "=f"(e) : "f"(-1.4426950408889634f * x));
    asm("rcp.approx.f32 %0, %1;" : "=f"(r) : "f"(1.f + e));
    return r;
}
__device__ __forceinline__ float ftanh(float x) {
    float e, r;
    asm("ex2.approx.f32 %0, %1;" : "=f"(e) : "f"(-2.8853900817779268f * x));
    asm("rcp.approx.f32 %0, %1;" : "=f"(r) : "f"(1.f + e));
    return fmaf(2.f, r, -1.f);
}
__device__ __forceinline__ void cp4(unsigned dst, const void* src) {
    asm volatile("cp.async.ca.shared.global [%0], [%1], 4;" :: "r"(dst), "l"(src));
}

// ---- scratch ----
__device__ float g_h0[BB * DH];
__device__ float g_Ga[100 * G3];
__device__ float g_Gt[4 * G3];
__device__ float g_Gx[BB * G3];

// ============================================================================
// K_PRO: merged prologue. grid 1128 x 384:
//   blocks [0,1024):  per-batch x_enc (local) -> h0 + Gx
//   blocks [1024,1124): tabA rows
//   blocks [1124,1128): tabT rows
// ============================================================================
__global__ void __launch_bounds__(384, 2)
k_pro(const float* __restrict__ x,  const float* __restrict__ Wx,
      const float* __restrict__ bx, const float* __restrict__ eps,
      const float* __restrict__ W0, const float* __restrict__ b0,
      const float* __restrict__ Ea, const float* __restrict__ Et,
      const float* __restrict__ Wih, const float* __restrict__ bih) {
    __shared__ float s0[64], xe[64], e0[16];
    int bid = blockIdx.x, tid = threadIdx.x;

    if (bid < 1024) {
        int b = bid;
        if (tid < 64)              s0[tid]      = x[b * 64 + tid];
        if (tid >= 64 && tid < 80) e0[tid - 64] = eps[(size_t)b * TT * DEPS + (tid - 64)];
        __syncthreads();
        if (tid < 64) {
            float acc = bx[tid];
            #pragma unroll
            for (int k = 0; k < 64; k++) acc = fmaf(Wx[tid * 64 + k], s0[k], acc);
            xe[tid] = acc;
        }
        __syncthreads();
        if (tid < 128) {
            float acc = b0[tid];
            #pragma unroll
            for (int k = 0; k < 64; k++) acc = fmaf(W0[tid * 80 + k], xe[k], acc);
            #pragma unroll
            for (int k = 0; k < 16; k++) acc = fmaf(W0[tid * 80 + 64 + k], e0[k], acc);
            g_h0[b * DH + tid] = tanhf(acc);
        }
        {
            float acc = bih[tid];
            #pragma unroll
            for (int k = 0; k < 64; k++) acc = fmaf(Wih[tid * 129 + 48 + k], xe[k], acc);
            g_Gx[b * G3 + tid] = acc;
        }
    } else if (bid < 1124) {
        int v = bid - 1024;
        if (tid < 32) s0[tid] = Ea[v * 32 + tid];
        __syncthreads();
        float acc = 0.f;
        #pragma unroll
        for (int k = 0; k < 32; k++) acc = fmaf(Wih[tid * 129 + k], s0[k], acc);
        g_Ga[v * G3 + tid] = acc;
    } else {
        int v = bid - 1124;
        if (tid < 16) s0[tid] = Et[v * 16 + tid];
        __syncthreads();
        float acc = 0.f;
        #pragma unroll
        for (int k = 0; k < 16; k++) acc = fmaf(Wih[tid * 129 + 32 + k], s0[k], acc);
        g_Gt[v * G3 + tid] = acc;
    }
}

// ============================================================================
// K_RNN: fused GRU scan, 152 blocks x 6-7 batch rows.
// ============================================================================
#define SMB (20288 * 4 + 6912 * 4 + (2176 + 640) * 2 + 1792 * 2 + 64)

__global__ void __launch_bounds__(384, 1)
k_rnn(const int* __restrict__ a, const int* __restrict__ tcat,
      const float* __restrict__ y, const float* __restrict__ eps,
      const float* __restrict__ Wih,
      const float* __restrict__ Whh, const float* __restrict__ bhh,
      const float* __restrict__ Wy,  const float* __restrict__ by,
      float* __restrict__ out) {
    extern __shared__ __align__(16) char smraw[];
    float* hs    = (float*)smraw;            //  896
    float* Gh    = hs + 896;                 // 3104
    float* sEps  = Gh + 3104;                // 3104
    float* sbhh  = sEps + 3104;              //  384
    float* Wys   = sbhh + 384;               //  128
    float* sGxb  = Wys + 128;                // 2688
    float* sGt   = sGxb + 2688;              // 1536
    float* swyg  = sGt + 1536;               //  384
    float* sGxs  = swyg + 384;               // 2688
    float* sga   = sGxs + 2688;              // 5376
    unsigned* sWeAhi = (unsigned*)(sga + 5376);  // 3456
    unsigned* sWeAlo = sWeAhi + 3456;            // 3456
    __nv_bfloat16* hhi   = (__nv_bfloat16*)(sWeAlo + 3456);  // 1088
    __nv_bfloat16* hlo   = hhi + 1088;                        // 1088
    __nv_bfloat16* epshi = hlo + 1088;                        //  320
    __nv_bfloat16* epslo = epshi + 320;                       //  320
    short* scode = (short*)(epslo + 320);                     // 1792

    int tid = threadIdx.x;
    int bid = blockIdx.x;
    int r0  = (bid * BB) / NB;
    int r1  = ((bid + 1) * BB) / NB;
    int nr  = r1 - r0;                    // 6 or 7
    int nu  = nr * 128;                   // h units in this block
    int warp = tid >> 5, lane = tid & 31;
    int grp = lane >> 2, q = lane & 3;

    // ---- Whh A-fragments (split bf16) resident in registers ----
    unsigned Ahi[2][8][4], Alo[2][8][4];
    #pragma unroll
    for (int mt = 0; mt < 2; mt++)
        #pragma unroll
        for (int kc = 0; kc < 8; kc++)
            #pragma unroll
            for (int i = 0; i < 4; i++) {
                int g = warp * 32 + mt * 16 + grp + ((i & 1) ? 8 : 0);
                int k = kc * 16 + 2 * q + ((i & 2) ? 8 : 0);
                float2 wv = *(const float2*)&Whh[g * 128 + k];
                Ahi[mt][kc][i] = bfsplit_hi(wv.x, wv.y);
                Alo[mt][kc][i] = bfsplit_lo(wv.x, wv.y);
            }

    // ---- prologue ----
    for (int i = tid; i < nr * 256; i += 384) {
        int r = i >> 8, s = i & 255;
        int av = a[(r0 + r) * TT + s];
        int tv = tcat[(r0 + r) * TT + s];
        int yb = (s == 0) ? 0 : (y[(r0 + r) * TT + s - 1] > 0.5f ? 1 : 0);
        scode[i] = (short)(av | (tv << 7) | (yb << 9));
    }
    for (int i = tid; i < nr * G3; i += 384) sGxb[i] = g_Gx[r0 * G3 + i];
    for (int i = tid; i < 1536; i += 384)    sGt[i]  = g_Gt[i];
    {
        int g = tid;
        swyg[g] = Wih[g * 129 + 128];
        #pragma unroll
        for (int k2 = 0; k2 < 8; k2++) {
            float w0 = Wih[g * 129 + 112 + 2 * k2];
            float w1 = Wih[g * 129 + 112 + 2 * k2 + 1];
            sWeAhi[g * 9 + k2] = bfsplit_hi(w0, w1);
            sWeAlo[g * 9 + k2] = bfsplit_lo(w0, w1);
        }
    }
    // zero-pad h and eps buffers (rows nr..7 stay zero forever).
    // NOTE: bounds are the exact array sizes (1088 / 320) — R10 overran into scode.
    for (int i = tid; i < 8 * HB_S; i += 384) { hhi[i] = __float2bfloat16(0.f); hlo[i] = hhi[i]; }
    for (int i = tid; i < 320; i += 384)      { epshi[i] = __float2bfloat16(0.f); epslo[i] = epshi[i]; }
    __syncthreads();
    for (int i = tid; i < nu; i += 384) {
        float h = g_h0[r0 * DH + i];
        hs[i] = h;
        int r = i >> 7, k = i & 127;
        __nv_bfloat16 hi = __float2bfloat16(h);
        hhi[r * HB_S + k] = hi;
        hlo[r * HB_S + k] = __float2bfloat16(h - __bfloat162float(hi));
    }
    sbhh[tid] = bhh[tid];
    if (tid < 128) Wys[tid] = Wy[tid];
    float by0 = by[0];
    __syncthreads();

    // sga[0], eps[0]
    #pragma unroll
    for (int r = 0; r < 7; r++)
        if (r < nr) {
            int ca = scode[r * 256] & 127;
            sga[r * 384 + tid] = g_Ga[ca * G3 + tid];
        }
    if (tid < 16 * nr) {
        int r = tid >> 4, k = tid & 15;
        float v = eps[((size_t)(r0 + r) * TT) * 16 + k];
        __nv_bfloat16 hi = __float2bfloat16(v);
        epshi[r * 20 + k] = hi;
        epslo[r * 20 + k] = __float2bfloat16(v - __bfloat162float(hi));
    }
    __syncthreads();

    unsigned sga_addr = (unsigned)__cvta_generic_to_shared(sga);

    for (int t = 0; t < TT; t++) {
        int buf = t & 1, nbuf = buf ^ 1;
        int tp1 = (t + 1) & 255;

        // ---- prefetch t+1 ----
        float epv = 0.f;
        if (tid < 16 * nr)
            epv = eps[((size_t)(r0 + (tid >> 4)) * TT + tp1) * 16 + (tid & 15)];
        #pragma unroll
        for (int r = 0; r < 7; r++)
            if (r < nr) {
                int ca = scode[r * 256 + tp1] & 127;
                cp4(sga_addr + (unsigned)(nbuf * 2688 + r * 384 + tid) * 4,
                    &g_Ga[ca * G3 + tid]);
            }
        asm volatile("cp.async.commit_group;");

        // ---- eps-MMA (K=16, split bf16) -> sEps ----
        {
            unsigned bh[2], bl[2];
            bh[0] = *(unsigned*)&epshi[buf * 160 + grp * 20 + 2 * q];
            bh[1] = *(unsigned*)&epshi[buf * 160 + grp * 20 + 2 * q + 8];
            bl[0] = *(unsigned*)&epslo[buf * 160 + grp * 20 + 2 * q];
            bl[1] = *(unsigned*)&epslo[buf * 160 + grp * 20 + 2 * q + 8];
            float ce0[4] = {0,0,0,0}, ce1[4] = {0,0,0,0};
            #pragma unroll
            for (int mt = 0; mt < 2; mt++) {
                int gb = warp * 32 + mt * 16;
                unsigned ah[4], al[4];
                ah[0] = sWeAhi[(gb + grp) * 9 + q];
                ah[1] = sWeAhi[(gb + grp + 8) * 9 + q];
                ah[2] = sWeAhi[(gb + grp) * 9 + q + 4];
                ah[3] = sWeAhi[(gb + grp + 8) * 9 + q + 4];
                al[0] = sWeAlo[(gb + grp) * 9 + q];
                al[1] = sWeAlo[(gb + grp + 8) * 9 + q];
                al[2] = sWeAlo[(gb + grp) * 9 + q + 4];
                al[3] = sWeAlo[(gb + grp + 8) * 9 + q + 4];
                float* d = mt ? ce1 : ce0;
                mma16816(d, ah, bh);
                mma16816(d, ah, bl);
                mma16816(d, al, bh);
            }
            int gsc = warp * 32 + grp;
            sEps[(2*q)   * GH_S + gsc]      = ce0[0];
            sEps[(2*q+1) * GH_S + gsc]      = ce0[1];
            sEps[(2*q)   * GH_S + gsc + 8]  = ce0[2];
            sEps[(2*q+1) * GH_S + gsc + 8]  = ce0[3];
            sEps[(2*q)   * GH_S + gsc + 16] = ce1[0];
            sEps[(2*q+1) * GH_S + gsc + 16] = ce1[1];
            sEps[(2*q)   * GH_S + gsc + 24] = ce1[2];
            sEps[(2*q+1) * GH_S + gsc + 24] = ce1[3];
        }

        // ---- h-MMA: gh = Whh @ h^T ----
        float c0a[4] = {0,0,0,0}, c0b[4] = {0,0,0,0};
        float c1a[4] = {0,0,0,0}, c1b[4] = {0,0,0,0};
        #pragma unroll
        for (int kc = 0; kc < 8; kc++) {
            int koff = kc * 16 + 2 * q;
            unsigned bhh2[2], bll[2];
            bhh2[0] = *(const unsigned*)&hhi[grp * HB_S + koff];
            bhh2[1] = *(const unsigned*)&hhi[grp * HB_S + koff + 8];
            bll[0]  = *(const unsigned*)&hlo[grp * HB_S + koff];
            bll[1]  = *(const unsigned*)&hlo[grp * HB_S + koff + 8];
            float* d0 = (kc & 1) ? c0b : c0a;
            float* d1 = (kc & 1) ? c1b : c1a;
            mma16816(d0, Ahi[0][kc], bhh2);
            mma16816(d1, Ahi[1][kc], bhh2);
            mma16816(d0, Alo[0][kc], bhh2);
            mma16816(d1, Alo[1][kc], bhh2);
            mma16816(d0, Ahi[0][kc], bll);
            mma16816(d1, Ahi[1][kc], bll);
        }
        {
            int gsc = warp * 32 + grp;
            Gh[(2*q)   * GH_S + gsc]      = c0a[0] + c0b[0];
            Gh[(2*q+1) * GH_S + gsc]      = c0a[1] + c0b[1];
            Gh[(2*q)   * GH_S + gsc + 8]  = c0a[2] + c0b[2];
            Gh[(2*q+1) * GH_S + gsc + 8]  = c0a[3] + c0b[3];
            Gh[(2*q)   * GH_S + gsc + 16] = c1a[0] + c1b[0];
            Gh[(2*q+1) * GH_S + gsc + 16] = c1a[1] + c1b[1];
            Gh[(2*q)   * GH_S + gsc + 24] = c1a[2] + c1b[2];
            Gh[(2*q+1) * GH_S + gsc + 24] = c1a[3] + c1b[3];
        }

        // ---- gx assembly (thread = gate, nr rows) ----
        asm volatile("cp.async.wait_group 1;");
        #pragma unroll
        for (int r = 0; r < 7; r++)
            if (r < nr) {
                int code = scode[r * 256 + t];
                float acc = sga[buf * 2688 + r * 384 + tid]
                          + sGt[((code >> 7) & 3) * G3 + tid]
                          + sGxb[r * 384 + tid];
                if (code & 512) acc += swyg[tid];
                sGxs[r * 384 + tid] = acc;
            }

        // ---- stage eps(t+1) split ----
        if (tid < 16 * nr) {
            int r = tid >> 4, k = tid & 15;
            __nv_bfloat16 hi = __float2bfloat16(epv);
            epshi[nbuf * 160 + r * 20 + k] = hi;
            epslo[nbuf * 160 + r * 20 + k] = __float2bfloat16(epv - __bfloat162float(hi));
        }
        __syncthreads();

        // ---- fused gates + h update ----
        #pragma unroll
        for (int it = 0; it < 3; it++) {
            int i = tid + it * 384;
            if (i >= nu) break;
            int r = i >> 7, j = i & 127;
            float ghr = Gh[r * GH_S + j]       + sbhh[j];
            float ghz = Gh[r * GH_S + j + 128] + sbhh[j + 128];
            float ghn = Gh[r * GH_S + j + 256] + sbhh[j + 256];
            float gxr = sGxs[r * 384 + j]       + sEps[r * GH_S + j];
            float gxz = sGxs[r * 384 + j + 128] + sEps[r * GH_S + j + 128];
            float gxn = sGxs[r * 384 + j + 256] + sEps[r * GH_S + j + 256];
            float rv = fsigmoid(gxr + ghr);
            float zv = fsigmoid(gxz + ghz);
            float nv = ftanh(gxn + rv * ghn);
            float hn = (1.f - zv) * nv + zv * hs[i];
            hs[i] = hn;
            __nv_bfloat16 hi = __float2bfloat16(hn);
            hhi[r * HB_S + j] = hi;
            hlo[r * HB_S + j] = __float2bfloat16(hn - __bfloat162float(hi));
        }
        __syncthreads();

        // ---- output epilogue ----
        if (warp < nr) {
            float s = 0.f;
            #pragma unroll
            for (int m = 0; m < 4; m++)
                s = fmaf(hs[warp * 128 + lane + m * 32], Wys[lane + m * 32], s);
            s += __shfl_down_sync(0xffffffffu, s, 16);
            s += __shfl_down_sync(0xffffffffu, s, 8);
            s += __shfl_down_sync(0xffffffffu, s, 4);
            s += __shfl_down_sync(0xffffffffu, s, 2);
            s += __shfl_down_sync(0xffffffffu, s, 1);
            if (lane == 0) {
                float logit = s + by0;
                size_t o = ((size_t)(r0 + warp) * TT + t) * 2;
                out[o]     = logit;
                out[o + 1] = fsigmoid(logit);
            }
        }
    }
    asm volatile("cp.async.wait_group 0;");
}

// ============================================================================
extern "C" void kernel_launch(void* const* d_in, const int* in_sizes, int n_in,
                              void* d_out, int out_size) {
    const float* x   = (const float*)d_in[0];
    const int*   a   = (const int*)  d_in[1];
    const int*   t   = (const int*)  d_in[2];
    const float* y   = (const float*)d_in[3];
    const float* eps = (const float*)d_in[5];
    const float* Wx  = (const float*)d_in[6];
    const float* bx  = (const float*)d_in[7];
    const float* Ea  = (const float*)d_in[8];
    const float* Et  = (const float*)d_in[9];
    const float* Wih = (const float*)d_in[10];
    const float* Whh = (const float*)d_in[11];
    const float* bih = (const float*)d_in[12];
    const float* bhh = (const float*)d_in[13];
    const float* W0  = (const float*)d_in[14];
    const float* b0  = (const float*)d_in[15];
    const float* Wy  = (const float*)d_in[16];
    const float* by  = (const float*)d_in[17];
    float* out = (float*)d_out;

    cudaFuncSetAttribute(k_rnn, cudaFuncAttributeMaxDynamicSharedMemorySize, SMB);

    k_pro<<<1128, 384>>>(x, Wx, bx, eps, W0, b0, Ea, Et, Wih, bih);
    k_rnn<<<NB, 384, SMB>>>(a, t, y, eps, Wih, Whh, bhh, Wy, by, out);
}

// round 12
// speedup vs baseline: 5.0551x; 1.1247x over previous
#include <cuda_runtime.h>
#include <cuda_bf16.h>
#include <math.h>

#define BB   1024
#define TT   256
#define DH   128
#define G3   384
#define DX   64
#define DEPS 16
#define NB   152
#define GH_S 388
#define HB_S 136

__device__ __forceinline__ void mma16816(float* c, const unsigned* a, const unsigned* b) {
    asm volatile(
        "mma.sync.aligned.m16n8k16.row.col.f32.bf16.bf16.f32 "
        "{%0,%1,%2,%3}, {%4,%5,%6,%7}, {%8,%9}, {%0,%1,%2,%3};"
        : "+f"(c[0]), "+f"(c[1]), "+f"(c[2]), "+f"(c[3])
        : "r"(a[0]), "r"(a[1]), "r"(a[2]), "r"(a[3]), "r"(b[0]), "r"(b[1]));
}
__device__ __forceinline__ unsigned bfsplit_hi(float x, float y) {
    __nv_bfloat162 p; p.x = __float2bfloat16(x); p.y = __float2bfloat16(y);
    return *(unsigned*)&p;
}
__device__ __forceinline__ unsigned bfsplit_lo(float x, float y) {
    __nv_bfloat162 p;
    p.x = __float2bfloat16(x - __bfloat162float(__float2bfloat16(x)));
    p.y = __float2bfloat16(y - __bfloat162float(__float2bfloat16(y)));
    return *(unsigned*)&p;
}
__device__ __forceinline__ float fsigmoid(float x) {
    float e, r;
    asm("ex2.approx.f32 %0, %1;" : "=f"(e) : "f"(-1.4426950408889634f * x));
    asm("rcp.approx.f32 %0, %1;" : "=f"(r) : "f"(1.f + e));
    return r;
}
__device__ __forceinline__ float ftanh(float x) {
    float e, r;
    asm("ex2.approx.f32 %0, %1;" : "=f"(e) : "f"(-2.8853900817779268f * x));
    asm("rcp.approx.f32 %0, %1;" : "=f"(r) : "f"(1.f + e));
    return fmaf(2.f, r, -1.f);
}
__device__ __forceinline__ void cp4(unsigned dst, const void* src) {
    asm volatile("cp.async.ca.shared.global [%0], [%1], 4;" :: "r"(dst), "l"(src));
}

// eps-MMA: sE[gate][row] = We . eps (split bf16)
__device__ __forceinline__ void eps_mma(
    const __nv_bfloat16* ehi, const __nv_bfloat16* elo,
    const unsigned* sWeAhi, const unsigned* sWeAlo,
    float* sE, int warp, int grp, int q) {
    unsigned bh[2], bl[2];
    bh[0] = *(const unsigned*)&ehi[grp * 20 + 2 * q];
    bh[1] = *(const unsigned*)&ehi[grp * 20 + 2 * q + 8];
    bl[0] = *(const unsigned*)&elo[grp * 20 + 2 * q];
    bl[1] = *(const unsigned*)&elo[grp * 20 + 2 * q + 8];
    float ce0[4] = {0,0,0,0}, ce1[4] = {0,0,0,0};
    #pragma unroll
    for (int mt = 0; mt < 2; mt++) {
        int gb = warp * 32 + mt * 16;
        unsigned ah[4], al[4];
        ah[0] = sWeAhi[(gb + grp) * 9 + q];
        ah[1] = sWeAhi[(gb + grp + 8) * 9 + q];
        ah[2] = sWeAhi[(gb + grp) * 9 + q + 4];
        ah[3] = sWeAhi[(gb + grp + 8) * 9 + q + 4];
        al[0] = sWeAlo[(gb + grp) * 9 + q];
        al[1] = sWeAlo[(gb + grp + 8) * 9 + q];
        al[2] = sWeAlo[(gb + grp) * 9 + q + 4];
        al[3] = sWeAlo[(gb + grp + 8) * 9 + q + 4];
        float* d = mt ? ce1 : ce0;
        mma16816(d, ah, bh);
        mma16816(d, ah, bl);
        mma16816(d, al, bh);
    }
    int gsc = warp * 32 + grp;
    sE[(2*q)   * GH_S + gsc]      = ce0[0];
    sE[(2*q+1) * GH_S + gsc]      = ce0[1];
    sE[(2*q)   * GH_S + gsc + 8]  = ce0[2];
    sE[(2*q+1) * GH_S + gsc + 8]  = ce0[3];
    sE[(2*q)   * GH_S + gsc + 16] = ce1[0];
    sE[(2*q+1) * GH_S + gsc + 16] = ce1[1];
    sE[(2*q)   * GH_S + gsc + 24] = ce1[2];
    sE[(2*q+1) * GH_S + gsc + 24] = ce1[3];
}

// ---- scratch ----
__device__ float g_h0[BB * DH];
__device__ float g_Ga[100 * G3];
__device__ float g_Gt[4 * G3];
__device__ float g_Gx[BB * G3];

// ============================================================================
// K_PRO: merged prologue (unchanged from R11)
// ============================================================================
__global__ void __launch_bounds__(384, 2)
k_pro(const float* __restrict__ x,  const float* __restrict__ Wx,
      const float* __restrict__ bx, const float* __restrict__ eps,
      const float* __restrict__ W0, const float* __restrict__ b0,
      const float* __restrict__ Ea, const float* __restrict__ Et,
      const float* __restrict__ Wih, const float* __restrict__ bih) {
    __shared__ float s0[64], xe[64], e0[16];
    int bid = blockIdx.x, tid = threadIdx.x;

    if (bid < 1024) {
        int b = bid;
        if (tid < 64)              s0[tid]      = x[b * 64 + tid];
        if (tid >= 64 && tid < 80) e0[tid - 64] = eps[(size_t)b * TT * DEPS + (tid - 64)];
        __syncthreads();
        if (tid < 64) {
            float acc = bx[tid];
            #pragma unroll
            for (int k = 0; k < 64; k++) acc = fmaf(Wx[tid * 64 + k], s0[k], acc);
            xe[tid] = acc;
        }
        __syncthreads();
        if (tid < 128) {
            float acc = b0[tid];
            #pragma unroll
            for (int k = 0; k < 64; k++) acc = fmaf(W0[tid * 80 + k], xe[k], acc);
            #pragma unroll
            for (int k = 0; k < 16; k++) acc = fmaf(W0[tid * 80 + 64 + k], e0[k], acc);
            g_h0[b * DH + tid] = tanhf(acc);
        }
        {
            float acc = bih[tid];
            #pragma unroll
            for (int k = 0; k < 64; k++) acc = fmaf(Wih[tid * 129 + 48 + k], xe[k], acc);
            g_Gx[b * G3 + tid] = acc;
        }
    } else if (bid < 1124) {
        int v = bid - 1024;
        if (tid < 32) s0[tid] = Ea[v * 32 + tid];
        __syncthreads();
        float acc = 0.f;
        #pragma unroll
        for (int k = 0; k < 32; k++) acc = fmaf(Wih[tid * 129 + k], s0[k], acc);
        g_Ga[v * G3 + tid] = acc;
    } else {
        int v = bid - 1124;
        if (tid < 16) s0[tid] = Et[v * 16 + tid];
        __syncthreads();
        float acc = 0.f;
        #pragma unroll
        for (int k = 0; k < 16; k++) acc = fmaf(Wih[tid * 129 + 32 + k], s0[k], acc);
        g_Gt[v * G3 + tid] = acc;
    }
}

// ============================================================================
// K_RNN: fused GRU scan, rebalanced phases.
// Phase 1: cp.async prefetch + h-MMA + Gh scatter (recurrence-critical only)
// Phase 2: EW (inline gx) + eps-MMA(t+1)
// ============================================================================
#define SMB (20704 * 4 + 6912 * 4 + (2176 + 640) * 2 + 1792 * 2 + 64)

__global__ void __launch_bounds__(384, 1)
k_rnn(const int* __restrict__ a, const int* __restrict__ tcat,
      const float* __restrict__ y, const float* __restrict__ eps,
      const float* __restrict__ Wih,
      const float* __restrict__ Whh, const float* __restrict__ bhh,
      const float* __restrict__ Wy,  const float* __restrict__ by,
      float* __restrict__ out) {
    extern __shared__ __align__(16) char smraw[];
    float* hs    = (float*)smraw;            //  896
    float* Gh    = hs + 896;                 // 3104
    float* sEps  = Gh + 3104;                // 6208 (double buffer)
    float* sbhh  = sEps + 6208;              //  384
    float* Wys   = sbhh + 384;               //  128
    float* sGxb  = Wys + 128;                // 2688
    float* sGt   = sGxb + 2688;              // 1536
    float* swyg  = sGt + 1536;               //  384
    float* sga   = swyg + 384;               // 5376 (double buffer)
    unsigned* sWeAhi = (unsigned*)(sga + 5376);  // 3456
    unsigned* sWeAlo = sWeAhi + 3456;            // 3456
    __nv_bfloat16* hhi   = (__nv_bfloat16*)(sWeAlo + 3456);  // 1088
    __nv_bfloat16* hlo   = hhi + 1088;                        // 1088
    __nv_bfloat16* epshi = hlo + 1088;                        //  320
    __nv_bfloat16* epslo = epshi + 320;                       //  320
    short* scode = (short*)(epslo + 320);                     // 1792

    int tid = threadIdx.x;
    int bid = blockIdx.x;
    int r0  = (bid * BB) / NB;
    int r1  = ((bid + 1) * BB) / NB;
    int nr  = r1 - r0;                    // 6 or 7
    int nu  = nr * 128;
    int warp = tid >> 5, lane = tid & 31;
    int grp = lane >> 2, q = lane & 3;

    // ---- Whh A-fragments (split bf16) resident in registers ----
    unsigned Ahi[2][8][4], Alo[2][8][4];
    #pragma unroll
    for (int mt = 0; mt < 2; mt++)
        #pragma unroll
        for (int kc = 0; kc < 8; kc++)
            #pragma unroll
            for (int i = 0; i < 4; i++) {
                int g = warp * 32 + mt * 16 + grp + ((i & 1) ? 8 : 0);
                int k = kc * 16 + 2 * q + ((i & 2) ? 8 : 0);
                float2 wv = *(const float2*)&Whh[g * 128 + k];
                Ahi[mt][kc][i] = bfsplit_hi(wv.x, wv.y);
                Alo[mt][kc][i] = bfsplit_lo(wv.x, wv.y);
            }

    // ---- prologue ----
    for (int i = tid; i < nr * 256; i += 384) {
        int r = i >> 8, s = i & 255;
        int av = a[(r0 + r) * TT + s];
        int tv = tcat[(r0 + r) * TT + s];
        int yb = (s == 0) ? 0 : (y[(r0 + r) * TT + s - 1] > 0.5f ? 1 : 0);
        scode[i] = (short)(av | (tv << 7) | (yb << 9));
    }
    for (int i = tid; i < nr * G3; i += 384) sGxb[i] = g_Gx[r0 * G3 + i];
    for (int i = tid; i < 1536; i += 384)    sGt[i]  = g_Gt[i];
    {
        int g = tid;
        swyg[g] = Wih[g * 129 + 128];
        #pragma unroll
        for (int k2 = 0; k2 < 8; k2++) {
            float w0 = Wih[g * 129 + 112 + 2 * k2];
            float w1 = Wih[g * 129 + 112 + 2 * k2 + 1];
            sWeAhi[g * 9 + k2] = bfsplit_hi(w0, w1);
            sWeAlo[g * 9 + k2] = bfsplit_lo(w0, w1);
        }
    }
    for (int i = tid; i < 8 * HB_S; i += 384) { hhi[i] = __float2bfloat16(0.f); hlo[i] = hhi[i]; }
    for (int i = tid; i < 320; i += 384)      { epshi[i] = __float2bfloat16(0.f); epslo[i] = epshi[i]; }
    __syncthreads();
    for (int i = tid; i < nu; i += 384) {
        float h = g_h0[r0 * DH + i];
        hs[i] = h;
        int r = i >> 7, k = i & 127;
        __nv_bfloat16 hi = __float2bfloat16(h);
        hhi[r * HB_S + k] = hi;
        hlo[r * HB_S + k] = __float2bfloat16(h - __bfloat162float(hi));
    }
    sbhh[tid] = bhh[tid];
    if (tid < 128) Wys[tid] = Wy[tid];
    float by0 = by[0];
    __syncthreads();

    // sga[0] (sync), epshi[0]
    #pragma unroll
    for (int r = 0; r < 7; r++)
        if (r < nr) {
            int ca = scode[r * 256] & 127;
            sga[r * 384 + tid] = g_Ga[ca * G3 + tid];
        }
    if (tid < 16 * nr) {
        int r = tid >> 4, k = tid & 15;
        float v = eps[((size_t)(r0 + r) * TT) * 16 + k];
        __nv_bfloat16 hi = __float2bfloat16(v);
        epshi[r * 20 + k] = hi;
        epslo[r * 20 + k] = __float2bfloat16(v - __bfloat162float(hi));
    }
    __syncthreads();
    // sEps[0] for t=0
    eps_mma(epshi, epslo, sWeAhi, sWeAlo, sEps, warp, grp, q);

    unsigned sga_addr = (unsigned)__cvta_generic_to_shared(sga);

    for (int t = 0; t < TT; t++) {
        int buf = t & 1, nbuf = buf ^ 1;
        int tp1 = (t + 1) & 255;

        // ================= PHASE 1 (recurrence-critical) =================
        float epv = 0.f;
        if (tid < 16 * nr)
            epv = eps[((size_t)(r0 + (tid >> 4)) * TT + tp1) * 16 + (tid & 15)];
        #pragma unroll
        for (int r = 0; r < 7; r++)
            if (r < nr) {
                int ca = scode[r * 256 + tp1] & 127;
                cp4(sga_addr + (unsigned)(nbuf * 2688 + r * 384 + tid) * 4,
                    &g_Ga[ca * G3 + tid]);
            }
        asm volatile("cp.async.commit_group;");

        // h-MMA: gh = Whh @ h^T
        float c0a[4] = {0,0,0,0}, c0b[4] = {0,0,0,0};
        float c1a[4] = {0,0,0,0}, c1b[4] = {0,0,0,0};
        #pragma unroll
        for (int kc = 0; kc < 8; kc++) {
            int koff = kc * 16 + 2 * q;
            unsigned bhh2[2], bll[2];
            bhh2[0] = *(const unsigned*)&hhi[grp * HB_S + koff];
            bhh2[1] = *(const unsigned*)&hhi[grp * HB_S + koff + 8];
            bll[0]  = *(const unsigned*)&hlo[grp * HB_S + koff];
            bll[1]  = *(const unsigned*)&hlo[grp * HB_S + koff + 8];
            float* d0 = (kc & 1) ? c0b : c0a;
            float* d1 = (kc & 1) ? c1b : c1a;
            mma16816(d0, Ahi[0][kc], bhh2);
            mma16816(d1, Ahi[1][kc], bhh2);
            mma16816(d0, Alo[0][kc], bhh2);
            mma16816(d1, Alo[1][kc], bhh2);
            mma16816(d0, Ahi[0][kc], bll);
            mma16816(d1, Ahi[1][kc], bll);
        }
        {
            int gsc = warp * 32 + grp;
            Gh[(2*q)   * GH_S + gsc]      = c0a[0] + c0b[0];
            Gh[(2*q+1) * GH_S + gsc]      = c0a[1] + c0b[1];
            Gh[(2*q)   * GH_S + gsc + 8]  = c0a[2] + c0b[2];
            Gh[(2*q+1) * GH_S + gsc + 8]  = c0a[3] + c0b[3];
            Gh[(2*q)   * GH_S + gsc + 16] = c1a[0] + c1b[0];
            Gh[(2*q+1) * GH_S + gsc + 16] = c1a[1] + c1b[1];
            Gh[(2*q)   * GH_S + gsc + 24] = c1a[2] + c1b[2];
            Gh[(2*q+1) * GH_S + gsc + 24] = c1a[3] + c1b[3];
        }

        asm volatile("cp.async.wait_group 1;");   // sga(t) complete
        // stage eps(t+1)
        if (tid < 16 * nr) {
            int r = tid >> 4, k = tid & 15;
            __nv_bfloat16 hi = __float2bfloat16(epv);
            epshi[nbuf * 160 + r * 20 + k] = hi;
            epslo[nbuf * 160 + r * 20 + k] = __float2bfloat16(epv - __bfloat162float(hi));
        }
        __syncthreads();

        // ================= PHASE 2 =================
        // EW with inline gx
        #pragma unroll
        for (int it = 0; it < 3; it++) {
            int i = tid + it * 384;
            if (i >= nu) break;
            int r = i >> 7, j = i & 127;
            int code = scode[r * 256 + t];
            int gt0 = ((code >> 7) & 3) * G3;
            const float* gab = sga + buf * 2688 + r * 384;
            const float* gxb = sGxb + r * 384;
            const float* se  = sEps + buf * 3104 + r * GH_S;
            float gxr = gab[j]       + sGt[gt0 + j]       + gxb[j]       + se[j];
            float gxz = gab[j + 128] + sGt[gt0 + j + 128] + gxb[j + 128] + se[j + 128];
            float gxn = gab[j + 256] + sGt[gt0 + j + 256] + gxb[j + 256] + se[j + 256];
            if (code & 512) {
                gxr += swyg[j]; gxz += swyg[j + 128]; gxn += swyg[j + 256];
            }
            float ghr = Gh[r * GH_S + j]       + sbhh[j];
            float ghz = Gh[r * GH_S + j + 128] + sbhh[j + 128];
            float ghn = Gh[r * GH_S + j + 256] + sbhh[j + 256];
            float rv = fsigmoid(gxr + ghr);
            float zv = fsigmoid(gxz + ghz);
            float nv = ftanh(gxn + rv * ghn);
            float hn = (1.f - zv) * nv + zv * hs[i];
            hs[i] = hn;
            __nv_bfloat16 hi = __float2bfloat16(hn);
            hhi[r * HB_S + j] = hi;
            hlo[r * HB_S + j] = __float2bfloat16(hn - __bfloat162float(hi));
        }

        // eps-MMA for step t+1 (h-independent; fills phase-2 slack)
        eps_mma(epshi + nbuf * 160, epslo + nbuf * 160,
                sWeAhi, sWeAlo, sEps + nbuf * 3104, warp, grp, q);
        __syncthreads();

        // ---- output epilogue (overlaps next phase 1) ----
        if (warp < nr) {
            float s = 0.f;
            #pragma unroll
            for (int m = 0; m < 4; m++)
                s = fmaf(hs[warp * 128 + lane + m * 32], Wys[lane + m * 32], s);
            s += __shfl_down_sync(0xffffffffu, s, 16);
            s += __shfl_down_sync(0xffffffffu, s, 8);
            s += __shfl_down_sync(0xffffffffu, s, 4);
            s += __shfl_down_sync(0xffffffffu, s, 2);
            s += __shfl_down_sync(0xffffffffu, s, 1);
            if (lane == 0) {
                float logit = s + by0;
                size_t o = ((size_t)(r0 + warp) * TT + t) * 2;
                out[o]     = logit;
                out[o + 1] = fsigmoid(logit);
            }
        }
    }
    asm volatile("cp.async.wait_group 0;");
}

// ============================================================================
extern "C" void kernel_launch(void* const* d_in, const int* in_sizes, int n_in,
                              void* d_out, int out_size) {
    const float* x   = (const float*)d_in[0];
    const int*   a   = (const int*)  d_in[1];
    const int*   t   = (const int*)  d_in[2];
    const float* y   = (const float*)d_in[3];
    const float* eps = (const float*)d_in[5];
    const float* Wx  = (const float*)d_in[6];
    const float* bx  = (const float*)d_in[7];
    const float* Ea  = (const float*)d_in[8];
    const float* Et  = (const float*)d_in[9];
    const float* Wih = (const float*)d_in[10];
    const float* Whh = (const float*)d_in[11];
    const float* bih = (const float*)d_in[12];
    const float* bhh = (const float*)d_in[13];
    const float* W0  = (const float*)d_in[14];
    const float* b0  = (const float*)d_in[15];
    const float* Wy  = (const float*)d_in[16];
    const float* by  = (const float*)d_in[17];
    float* out = (float*)d_out;

    cudaFuncSetAttribute(k_rnn, cudaFuncAttributeMaxDynamicSharedMemorySize, SMB);

    k_pro<<<1128, 384>>>(x, Wx, bx, eps, W0, b0, Ea, Et, Wih, bih);
    k_rnn<<<NB, 384, SMB>>>(a, t, y, eps, Wih, Whh, bhh, Wy, by, out);
}

// round 13
// speedup vs baseline: 5.2014x; 1.0289x over previous
#include <cuda_runtime.h>
#include <cuda_bf16.h>
#include <math.h>

#define BB   1024
#define TT   256
#define DH   128
#define G3   384
#define DX   64
#define DEPS 16
#define NB   152
#define GH_S 388
#define HB_S 136

__device__ __forceinline__ void mma16816(float* c, const unsigned* a, const unsigned* b) {
    asm volatile(
        "mma.sync.aligned.m16n8k16.row.col.f32.bf16.bf16.f32 "
        "{%0,%1,%2,%3}, {%4,%5,%6,%7}, {%8,%9}, {%0,%1,%2,%3};"
        : "+f"(c[0]), "+f"(c[1]), "+f"(c[2]), "+f"(c[3])
        : "r"(a[0]), "r"(a[1]), "r"(a[2]), "r"(a[3]), "r"(b[0]), "r"(b[1]));
}
__device__ __forceinline__ unsigned bfsplit_hi(float x, float y) {
    __nv_bfloat162 p; p.x = __float2bfloat16(x); p.y = __float2bfloat16(y);
    return *(unsigned*)&p;
}
__device__ __forceinline__ unsigned bfsplit_lo(float x, float y) {
    __nv_bfloat162 p;
    p.x = __float2bfloat16(x - __bfloat162float(__float2bfloat16(x)));
    p.y = __float2bfloat16(y - __bfloat162float(__float2bfloat16(y)));
    return *(unsigned*)&p;
}
__device__ __forceinline__ float fsigmoid(float x) {
    float e, r;
    asm("ex2.approx.f32 %0, %1;" : "=f"(e) : "f"(-1.4426950408889634f * x));
    asm("rcp.approx.f32 %0, %1;" : "=f"(r) : "f"(1.f + e));
    return r;
}
__device__ __forceinline__ float ftanh(float x) {
    float e, r;
    asm("ex2.approx.f32 %0, %1;" : "=f"(e) : "f"(-2.8853900817779268f * x));
    asm("rcp.approx.f32 %0, %1;" : "=f"(r) : "f"(1.f + e));
    return fmaf(2.f, r, -1.f);
}
__device__ __forceinline__ void cp4(unsigned dst, const void* src) {
    asm volatile("cp.async.ca.shared.global [%0], [%1], 4;" :: "r"(dst), "l"(src));
}

// eps-MMA: sE[gate][row] = We . eps (split bf16)
__device__ __forceinline__ void eps_mma(
    const __nv_bfloat16* ehi, const __nv_bfloat16* elo,
    const unsigned* sWeAhi, const unsigned* sWeAlo,
    float* sE, int warp, int grp, int q) {
    unsigned bh[2], bl[2];
    bh[0] = *(const unsigned*)&ehi[grp * 20 + 2 * q];
    bh[1] = *(const unsigned*)&ehi[grp * 20 + 2 * q + 8];
    bl[0] = *(const unsigned*)&elo[grp * 20 + 2 * q];
    bl[1] = *(const unsigned*)&elo[grp * 20 + 2 * q + 8];
    float ce0[4] = {0,0,0,0}, ce1[4] = {0,0,0,0};
    #pragma unroll
    for (int mt = 0; mt < 2; mt++) {
        int gb = warp * 32 + mt * 16;
        unsigned ah[4], al[4];
        ah[0] = sWeAhi[(gb + grp) * 9 + q];
        ah[1] = sWeAhi[(gb + grp + 8) * 9 + q];
        ah[2] = sWeAhi[(gb + grp) * 9 + q + 4];
        ah[3] = sWeAhi[(gb + grp + 8) * 9 + q + 4];
        al[0] = sWeAlo[(gb + grp) * 9 + q];
        al[1] = sWeAlo[(gb + grp + 8) * 9 + q];
        al[2] = sWeAlo[(gb + grp) * 9 + q + 4];
        al[3] = sWeAlo[(gb + grp + 8) * 9 + q + 4];
        float* d = mt ? ce1 : ce0;
        mma16816(d, ah, bh);
        mma16816(d, ah, bl);
        mma16816(d, al, bh);
    }
    int gsc = warp * 32 + grp;
    sE[(2*q)   * GH_S + gsc]      = ce0[0];
    sE[(2*q+1) * GH_S + gsc]      = ce0[1];
    sE[(2*q)   * GH_S + gsc + 8]  = ce0[2];
    sE[(2*q+1) * GH_S + gsc + 8]  = ce0[3];
    sE[(2*q)   * GH_S + gsc + 16] = ce1[0];
    sE[(2*q+1) * GH_S + gsc + 16] = ce1[1];
    sE[(2*q)   * GH_S + gsc + 24] = ce1[2];
    sE[(2*q+1) * GH_S + gsc + 24] = ce1[3];
}

// ---- scratch ----
__device__ float g_h0[BB * DH];
__device__ float g_Ga3[800 * G3];   // full categorical table: idx = a + 100*t + 400*y
__device__ float g_Gx[BB * G3];     // per-batch x term + bih (+ bhh for r,z gates)

// ============================================================================
// K_PRO: merged prologue. grid 1824 x 384:
//   [0,1024):    per-batch x_enc -> h0 + Gx (bih + bhh_{r,z} folded)
//   [1024,1824): Ga3 code table rows
// ============================================================================
__global__ void __launch_bounds__(384, 2)
k_pro(const float* __restrict__ x,  const float* __restrict__ Wx,
      const float* __restrict__ bx, const float* __restrict__ eps,
      const float* __restrict__ W0, const float* __restrict__ b0,
      const float* __restrict__ Ea, const float* __restrict__ Et,
      const float* __restrict__ Wih, const float* __restrict__ bih,
      const float* __restrict__ bhh) {
    __shared__ float s0[64], xe[64], e0[16];
    int bid = blockIdx.x, tid = threadIdx.x;

    if (bid < 1024) {
        int b = bid;
        if (tid < 64)              s0[tid]      = x[b * 64 + tid];
        if (tid >= 64 && tid < 80) e0[tid - 64] = eps[(size_t)b * TT * DEPS + (tid - 64)];
        __syncthreads();
        if (tid < 64) {
            float acc = bx[tid];
            #pragma unroll
            for (int k = 0; k < 64; k++) acc = fmaf(Wx[tid * 64 + k], s0[k], acc);
            xe[tid] = acc;
        }
        __syncthreads();
        if (tid < 128) {
            float acc = b0[tid];
            #pragma unroll
            for (int k = 0; k < 64; k++) acc = fmaf(W0[tid * 80 + k], xe[k], acc);
            #pragma unroll
            for (int k = 0; k < 16; k++) acc = fmaf(W0[tid * 80 + 64 + k], e0[k], acc);
            g_h0[b * DH + tid] = tanhf(acc);
        }
        {
            float acc = bih[tid] + ((tid < 256) ? bhh[tid] : 0.f);
            #pragma unroll
            for (int k = 0; k < 64; k++) acc = fmaf(Wih[tid * 129 + 48 + k], xe[k], acc);
            g_Gx[b * G3 + tid] = acc;
        }
    } else {
        int v = bid - 1024;          // 0..799
        int yb = v / 400;
        int rem = v - yb * 400;
        int tv = rem / 100;
        int av = rem - tv * 100;
        if (tid < 32)               s0[tid]      = Ea[av * 32 + tid];
        if (tid >= 32 && tid < 48)  s0[tid]      = Et[tv * 16 + (tid - 32)];
        __syncthreads();
        float acc = yb ? Wih[tid * 129 + 128] : 0.f;
        #pragma unroll
        for (int k = 0; k < 32; k++) acc = fmaf(Wih[tid * 129 + k], s0[k], acc);
        #pragma unroll
        for (int k = 0; k < 16; k++) acc = fmaf(Wih[tid * 129 + 32 + k], s0[32 + k], acc);
        g_Ga3[v * G3 + tid] = acc;
    }
}

// ============================================================================
// K_RNN: fused GRU scan. Phase 1 = prefetch + h-MMA + scatter;
// Phase 2 = EW (gx = sga + sGxb + sEps) + eps-MMA(t+1).
// ============================================================================
#define SMB (18784 * 4 + 6912 * 4 + 2816 * 2 + 1792 * 2 + 64)

__global__ void __launch_bounds__(384, 1)
k_rnn(const int* __restrict__ a, const int* __restrict__ tcat,
      const float* __restrict__ y, const float* __restrict__ eps,
      const float* __restrict__ Wih,
      const float* __restrict__ Whh, const float* __restrict__ bhh,
      const float* __restrict__ Wy,  const float* __restrict__ by,
      float* __restrict__ out) {
    extern __shared__ __align__(16) char smraw[];
    float* hs    = (float*)smraw;            //  896
    float* Gh    = hs + 896;                 // 3104
    float* sEps  = Gh + 3104;                // 6208 (double buffer)
    float* sbhh  = sEps + 6208;              //  384 (only n-part used)
    float* Wys   = sbhh + 384;               //  128
    float* sGxb  = Wys + 128;                // 2688
    float* sga   = sGxb + 2688;              // 5376 (double buffer)
    unsigned* sWeAhi = (unsigned*)(sga + 5376);  // 3456
    unsigned* sWeAlo = sWeAhi + 3456;            // 3456
    __nv_bfloat16* hhi   = (__nv_bfloat16*)(sWeAlo + 3456);  // 1088
    __nv_bfloat16* hlo   = hhi + 1088;                        // 1088
    __nv_bfloat16* epshi = hlo + 1088;                        //  320
    __nv_bfloat16* epslo = epshi + 320;                       //  320
    short* scode = (short*)(epslo + 320);                     // 1792

    int tid = threadIdx.x;
    int bid = blockIdx.x;
    int r0  = (bid * BB) / NB;
    int r1  = ((bid + 1) * BB) / NB;
    int nr  = r1 - r0;
    int nu  = nr * 128;
    int warp = tid >> 5, lane = tid & 31;
    int grp = lane >> 2, q = lane & 3;

    // ---- Whh A-fragments (split bf16) resident in registers ----
    unsigned Ahi[2][8][4], Alo[2][8][4];
    #pragma unroll
    for (int mt = 0; mt < 2; mt++)
        #pragma unroll
        for (int kc = 0; kc < 8; kc++)
            #pragma unroll
            for (int i = 0; i < 4; i++) {
                int g = warp * 32 + mt * 16 + grp + ((i & 1) ? 8 : 0);
                int k = kc * 16 + 2 * q + ((i & 2) ? 8 : 0);
                float2 wv = *(const float2*)&Whh[g * 128 + k];
                Ahi[mt][kc][i] = bfsplit_hi(wv.x, wv.y);
                Alo[mt][kc][i] = bfsplit_lo(wv.x, wv.y);
            }

    // ---- prologue ----
    for (int i = tid; i < nr * 256; i += 384) {
        int r = i >> 8, s = i & 255;
        int av = a[(r0 + r) * TT + s];
        int tv = tcat[(r0 + r) * TT + s];
        int yb = (s == 0) ? 0 : (y[(r0 + r) * TT + s - 1] > 0.5f ? 1 : 0);
        scode[i] = (short)(av + 100 * tv + 400 * yb);
    }
    for (int i = tid; i < nr * G3; i += 384) sGxb[i] = g_Gx[r0 * G3 + i];
    {
        int g = tid;
        #pragma unroll
        for (int k2 = 0; k2 < 8; k2++) {
            float w0 = Wih[g * 129 + 112 + 2 * k2];
            float w1 = Wih[g * 129 + 112 + 2 * k2 + 1];
            sWeAhi[g * 9 + k2] = bfsplit_hi(w0, w1);
            sWeAlo[g * 9 + k2] = bfsplit_lo(w0, w1);
        }
    }
    for (int i = tid; i < 8 * HB_S; i += 384) { hhi[i] = __float2bfloat16(0.f); hlo[i] = hhi[i]; }
    for (int i = tid; i < 320; i += 384)      { epshi[i] = __float2bfloat16(0.f); epslo[i] = epshi[i]; }
    __syncthreads();
    for (int i = tid; i < nu; i += 384) {
        float h = g_h0[r0 * DH + i];
        hs[i] = h;
        int r = i >> 7, k = i & 127;
        __nv_bfloat16 hi = __float2bfloat16(h);
        hhi[r * HB_S + k] = hi;
        hlo[r * HB_S + k] = __float2bfloat16(h - __bfloat162float(hi));
    }
    sbhh[tid] = bhh[tid];
    if (tid < 128) Wys[tid] = Wy[tid];
    float by0 = by[0];
    __syncthreads();

    // sga[0] (sync), epshi[0]
    #pragma unroll
    for (int r = 0; r < 7; r++)
        if (r < nr) {
            int ca = scode[r * 256];
            sga[r * 384 + tid] = g_Ga3[ca * G3 + tid];
        }
    if (tid < 16 * nr) {
        int r = tid >> 4, k = tid & 15;
        float v = eps[((size_t)(r0 + r) * TT) * 16 + k];
        __nv_bfloat16 hi = __float2bfloat16(v);
        epshi[r * 20 + k] = hi;
        epslo[r * 20 + k] = __float2bfloat16(v - __bfloat162float(hi));
    }
    __syncthreads();
    eps_mma(epshi, epslo, sWeAhi, sWeAlo, sEps, warp, grp, q);

    unsigned sga_addr = (unsigned)__cvta_generic_to_shared(sga);

    for (int t = 0; t < TT; t++) {
        int buf = t & 1, nbuf = buf ^ 1;
        int tp1 = (t + 1) & 255;

        // ================= PHASE 1 (recurrence-critical) =================
        float epv = 0.f;
        if (tid < 16 * nr)
            epv = eps[((size_t)(r0 + (tid >> 4)) * TT + tp1) * 16 + (tid & 15)];
        #pragma unroll
        for (int r = 0; r < 7; r++)
            if (r < nr) {
                int ca = scode[r * 256 + tp1];
                cp4(sga_addr + (unsigned)(nbuf * 2688 + r * 384 + tid) * 4,
                    &g_Ga3[ca * G3 + tid]);
            }
        asm volatile("cp.async.commit_group;");

        // h-MMA: gh = Whh @ h^T
        float c0a[4] = {0,0,0,0}, c0b[4] = {0,0,0,0};
        float c1a[4] = {0,0,0,0}, c1b[4] = {0,0,0,0};
        #pragma unroll
        for (int kc = 0; kc < 8; kc++) {
            int koff = kc * 16 + 2 * q;
            unsigned bhh2[2], bll[2];
            bhh2[0] = *(const unsigned*)&hhi[grp * HB_S + koff];
            bhh2[1] = *(const unsigned*)&hhi[grp * HB_S + koff + 8];
            bll[0]  = *(const unsigned*)&hlo[grp * HB_S + koff];
            bll[1]  = *(const unsigned*)&hlo[grp * HB_S + koff + 8];
            float* d0 = (kc & 1) ? c0b : c0a;
            float* d1 = (kc & 1) ? c1b : c1a;
            mma16816(d0, Ahi[0][kc], bhh2);
            mma16816(d1, Ahi[1][kc], bhh2);
            mma16816(d0, Alo[0][kc], bhh2);
            mma16816(d1, Alo[1][kc], bhh2);
            mma16816(d0, Ahi[0][kc], bll);
            mma16816(d1, Ahi[1][kc], bll);
        }
        {
            int gsc = warp * 32 + grp;
            Gh[(2*q)   * GH_S + gsc]      = c0a[0] + c0b[0];
            Gh[(2*q+1) * GH_S + gsc]      = c0a[1] + c0b[1];
            Gh[(2*q)   * GH_S + gsc + 8]  = c0a[2] + c0b[2];
            Gh[(2*q+1) * GH_S + gsc + 8]  = c0a[3] + c0b[3];
            Gh[(2*q)   * GH_S + gsc + 16] = c1a[0] + c1b[0];
            Gh[(2*q+1) * GH_S + gsc + 16] = c1a[1] + c1b[1];
            Gh[(2*q)   * GH_S + gsc + 24] = c1a[2] + c1b[2];
            Gh[(2*q+1) * GH_S + gsc + 24] = c1a[3] + c1b[3];
        }

        asm volatile("cp.async.wait_group 1;");
        if (tid < 16 * nr) {
            int r = tid >> 4, k = tid & 15;
            __nv_bfloat16 hi = __float2bfloat16(epv);
            epshi[nbuf * 160 + r * 20 + k] = hi;
            epslo[nbuf * 160 + r * 20 + k] = __float2bfloat16(epv - __bfloat162float(hi));
        }
        __syncthreads();

        // ================= PHASE 2 =================
        #pragma unroll
        for (int it = 0; it < 3; it++) {
            int i = tid + it * 384;
            if (i >= nu) break;
            int r = i >> 7, j = i & 127;
            const float* gab = sga + buf * 2688 + r * 384;
            const float* gxb = sGxb + r * 384;
            const float* se  = sEps + buf * 3104 + r * GH_S;
            float gxr = gab[j]       + gxb[j]       + se[j];
            float gxz = gab[j + 128] + gxb[j + 128] + se[j + 128];
            float gxn = gab[j + 256] + gxb[j + 256] + se[j + 256];
            float ghr = Gh[r * GH_S + j];
            float ghz = Gh[r * GH_S + j + 128];
            float ghn = Gh[r * GH_S + j + 256] + sbhh[j + 256];
            float rv = fsigmoid(gxr + ghr);
            float zv = fsigmoid(gxz + ghz);
            float nv = ftanh(gxn + rv * ghn);
            float hn = (1.f - zv) * nv + zv * hs[i];
            hs[i] = hn;
            __nv_bfloat16 hi = __float2bfloat16(hn);
            hhi[r * HB_S + j] = hi;
            hlo[r * HB_S + j] = __float2bfloat16(hn - __bfloat162float(hi));
        }

        eps_mma(epshi + nbuf * 160, epslo + nbuf * 160,
                sWeAhi, sWeAlo, sEps + nbuf * 3104, warp, grp, q);
        __syncthreads();

        // ---- output epilogue ----
        if (warp < nr) {
            float s = 0.f;
            #pragma unroll
            for (int m = 0; m < 4; m++)
                s = fmaf(hs[warp * 128 + lane + m * 32], Wys[lane + m * 32], s);
            s += __shfl_down_sync(0xffffffffu, s, 16);
            s += __shfl_down_sync(0xffffffffu, s, 8);
            s += __shfl_down_sync(0xffffffffu, s, 4);
            s += __shfl_down_sync(0xffffffffu, s, 2);
            s += __shfl_down_sync(0xffffffffu, s, 1);
            if (lane == 0) {
                float logit = s + by0;
                size_t o = ((size_t)(r0 + warp) * TT + t) * 2;
                out[o]     = logit;
                out[o + 1] = fsigmoid(logit);
            }
        }
    }
    asm volatile("cp.async.wait_group 0;");
}

// ============================================================================
extern "C" void kernel_launch(void* const* d_in, const int* in_sizes, int n_in,
                              void* d_out, int out_size) {
    const float* x   = (const float*)d_in[0];
    const int*   a   = (const int*)  d_in[1];
    const int*   t   = (const int*)  d_in[2];
    const float* y   = (const float*)d_in[3];
    const float* eps = (const float*)d_in[5];
    const float* Wx  = (const float*)d_in[6];
    const float* bx  = (const float*)d_in[7];
    const float* Ea  = (const float*)d_in[8];
    const float* Et  = (const float*)d_in[9];
    const float* Wih = (const float*)d_in[10];
    const float* Whh = (const float*)d_in[11];
    const float* bih = (const float*)d_in[12];
    const float* bhh = (const float*)d_in[13];
    const float* W0  = (const float*)d_in[14];
    const float* b0  = (const float*)d_in[15];
    const float* Wy  = (const float*)d_in[16];
    const float* by  = (const float*)d_in[17];
    float* out = (float*)d_out;

    cudaFuncSetAttribute(k_rnn, cudaFuncAttributeMaxDynamicSharedMemorySize, SMB);

    k_pro<<<1824, 384>>>(x, Wx, bx, eps, W0, b0, Ea, Et, Wih, bih, bhh);
    k_rnn<<<NB, 384, SMB>>>(a, t, y, eps, Wih, Whh, bhh, Wy, by, out);
}